// round 3
// baseline (speedup 1.0000x reference)
#include <cuda_runtime.h>
#include <cuda_bf16.h>
#include <cstdint>

#define D      768
#define KP     256
#define M_TILE 128

// Scratch (module-load allocated, not cudaMalloc)
__device__ __align__(16) __nv_bfloat16 g_pn[KP * D];    // normalized prototypes [k][d]
__device__ __align__(16) __nv_bfloat16 g_pwt[D * KP];   // (P @ W^T / K)^T : [e][k]

// ---------------------------------------------------------------------------
// Kernel 1: normalize prototypes -> bf16
// ---------------------------------------------------------------------------
__global__ void pn_kernel(const float* __restrict__ P) {
    __shared__ float red[8];
    int k = blockIdx.x;
    const float* row = P + k * D;
    float s = 0.f;
    for (int d = threadIdx.x; d < D; d += 256) { float v = row[d]; s += v * v; }
#pragma unroll
    for (int o = 16; o; o >>= 1) s += __shfl_xor_sync(0xffffffffu, s, o);
    if ((threadIdx.x & 31) == 0) red[threadIdx.x >> 5] = s;
    __syncthreads();
    if (threadIdx.x == 0) {
        float t = 0.f;
#pragma unroll
        for (int i = 0; i < 8; ++i) t += red[i];
        red[0] = 1.f / fmaxf(sqrtf(t), 1e-12f);
    }
    __syncthreads();
    float iv = red[0];
    for (int d = threadIdx.x; d < D; d += 256)
        g_pn[k * D + d] = __float2bfloat16(row[d] * iv);
}

// ---------------------------------------------------------------------------
// Kernel 2: PWT[e][k] = (1/K) * sum_d P[k][d] * W[e][d]   (bf16 output)
// grid = 192 blocks (4 e-rows each), 256 threads (thread = k)
// ---------------------------------------------------------------------------
__global__ void pwt_kernel(const float* __restrict__ P, const float* __restrict__ W) {
    __shared__ float Pt[256 * 33];
    __shared__ float Wt[4 * 33];
    int e0 = blockIdx.x * 4;
    int k  = threadIdx.x;
    float a0 = 0.f, a1 = 0.f, a2 = 0.f, a3 = 0.f;
    for (int dc = 0; dc < D; dc += 32) {
#pragma unroll
        for (int it = 0; it < 32; ++it) {
            int idx = threadIdx.x + 256 * it;   // 8192 = 256 rows x 32 cols
            int row = idx >> 5, d = idx & 31;
            Pt[row * 33 + d] = P[row * D + dc + d];
        }
        if (threadIdx.x < 128) {
            int e = threadIdx.x >> 5, d = threadIdx.x & 31;
            Wt[e * 33 + d] = W[(e0 + e) * D + dc + d];
        }
        __syncthreads();
#pragma unroll
        for (int d = 0; d < 32; ++d) {
            float p = Pt[k * 33 + d];
            a0 += p * Wt[0 * 33 + d];
            a1 += p * Wt[1 * 33 + d];
            a2 += p * Wt[2 * 33 + d];
            a3 += p * Wt[3 * 33 + d];
        }
        __syncthreads();
    }
    const float sc = 1.f / 256.f;
    g_pwt[(e0 + 0) * KP + k] = __float2bfloat16(a0 * sc);
    g_pwt[(e0 + 1) * KP + k] = __float2bfloat16(a1 * sc);
    g_pwt[(e0 + 2) * KP + k] = __float2bfloat16(a2 * sc);
    g_pwt[(e0 + 3) * KP + k] = __float2bfloat16(a3 * sc);
}

// ---------------------------------------------------------------------------
// Fused main kernel
// ---------------------------------------------------------------------------
__device__ __forceinline__ void mma_bf16(float& c0, float& c1, float& c2, float& c3,
                                         uint32_t a0, uint32_t a1, uint32_t a2, uint32_t a3,
                                         uint32_t b0, uint32_t b1) {
    asm volatile(
        "mma.sync.aligned.m16n8k16.row.col.f32.bf16.bf16.f32 "
        "{%0,%1,%2,%3}, {%4,%5,%6,%7}, {%8,%9}, {%0,%1,%2,%3};\n"
        : "+f"(c0), "+f"(c1), "+f"(c2), "+f"(c3)
        : "r"(a0), "r"(a1), "r"(a2), "r"(a3), "r"(b0), "r"(b1));
}

__device__ __forceinline__ uint32_t pack_bf16x2(float lo, float hi) {
    __nv_bfloat162 h = __float22bfloat162_rn(make_float2(lo, hi));
    return *reinterpret_cast<uint32_t*>(&h);
}

// smem layout (dynamic):
//   [0,512)         : float inv[128]
//   [1024, +67584)  : Psm  bf16 [128][264]   (prob)
//   [68608, +67584) : union { phase1: Asm [128][72] + Bsm [256][72] ; phase3: PWsm [128][264] }
#define SMEM_MAIN (1024 + 128 * 264 * 2 + 128 * 264 * 2)

__global__ __launch_bounds__(256, 1)
void main_kernel(const float* __restrict__ x, const float* __restrict__ bias,
                 float* __restrict__ out) {
    extern __shared__ char smem[];
    float*         inv = reinterpret_cast<float*>(smem);
    __nv_bfloat16* Psm = reinterpret_cast<__nv_bfloat16*>(smem + 1024);
    char*          ub  = smem + 1024 + 128 * 264 * 2;
    __nv_bfloat16* Asm = reinterpret_cast<__nv_bfloat16*>(ub);
    __nv_bfloat16* Bsm = reinterpret_cast<__nv_bfloat16*>(ub + 128 * 72 * 2);
    __nv_bfloat16* PWs = reinterpret_cast<__nv_bfloat16*>(ub);

    const int tid  = threadIdx.x;
    const int w    = tid >> 5;
    const int lane = tid & 31;
    const int g    = lane >> 2;
    const int q    = lane & 3;
    const long m0  = (long)blockIdx.x * M_TILE;

    const int SA = 72, SB = 72, SP = 264, SW = 264;

    // ---------- Phase 0: row norms (warp w owns rows w*16 .. w*16+15) ----------
    for (int i = 0; i < 16; ++i) {
        int row = w * 16 + i;
        const float4* xr = reinterpret_cast<const float4*>(x + (m0 + row) * D);
        float s = 0.f;
#pragma unroll
        for (int j = 0; j < 6; ++j) {
            float4 v = xr[lane + 32 * j];
            s += v.x * v.x + v.y * v.y + v.z * v.z + v.w * v.w;
        }
#pragma unroll
        for (int o = 16; o; o >>= 1) s += __shfl_xor_sync(0xffffffffu, s, o);
        if (lane == 0) inv[row] = 1.f / fmaxf(sqrtf(s), 1e-12f);
    }
    __syncthreads();

    // ---------- Phase 1: sim[128][256] = xn @ pn^T ----------
    // warp w computes rows [w*16, w*16+16) x all 256 cols
    float acc[32][4];
#pragma unroll
    for (int nt = 0; nt < 32; ++nt)
#pragma unroll
        for (int j = 0; j < 4; ++j) acc[nt][j] = 0.f;

    for (int kc = 0; kc < D; kc += 64) {
        // A chunk: xn[128][64] bf16  (2048 float4 loads -> 2048 uint2 stores)
#pragma unroll
        for (int it = 0; it < 8; ++it) {
            int idx = tid + 256 * it;         // 0..2047, 16 float4 per row
            int row = idx >> 4;
            int c4  = idx & 15;
            float4 v = *reinterpret_cast<const float4*>(x + (m0 + row) * D + kc + c4 * 4);
            float iv = inv[row];
            uint32_t p0 = pack_bf16x2(v.x * iv, v.y * iv);
            uint32_t p1 = pack_bf16x2(v.z * iv, v.w * iv);
            *reinterpret_cast<uint2*>(Asm + row * SA + c4 * 4) = make_uint2(p0, p1);
        }
        // B chunk: pn[256][64] bf16 = 2048 uint4, 8 uint4 per row
#pragma unroll
        for (int it = 0; it < 8; ++it) {
            int idx = tid + 256 * it;         // 0..2047
            int row = idx >> 3;               // 0..255
            int c8  = idx & 7;                // 8 uint4 per row (64 bf16)
            uint4 v = *reinterpret_cast<const uint4*>(g_pn + row * D + kc + c8 * 8);
            *reinterpret_cast<uint4*>(Bsm + row * SB + c8 * 8) = v;
        }
        __syncthreads();
#pragma unroll
        for (int ks = 0; ks < 4; ++ks) {
            int kb = ks * 16;
            const __nv_bfloat16* Ab = Asm + (w * 16 + g) * SA + kb + 2 * q;
            uint32_t a0 = *reinterpret_cast<const uint32_t*>(Ab);
            uint32_t a1 = *reinterpret_cast<const uint32_t*>(Ab + 8 * SA);
            uint32_t a2 = *reinterpret_cast<const uint32_t*>(Ab + 8);
            uint32_t a3 = *reinterpret_cast<const uint32_t*>(Ab + 8 * SA + 8);
#pragma unroll
            for (int nt = 0; nt < 32; ++nt) {
                const __nv_bfloat16* Bb = Bsm + (nt * 8 + g) * SB + kb + 2 * q;
                uint32_t b0 = *reinterpret_cast<const uint32_t*>(Bb);
                uint32_t b1 = *reinterpret_cast<const uint32_t*>(Bb + 8);
                mma_bf16(acc[nt][0], acc[nt][1], acc[nt][2], acc[nt][3],
                         a0, a1, a2, a3, b0, b1);
            }
        }
        __syncthreads();
    }

    // ---------- Phase 2: softmax in registers ----------
    // lane owns rows r0 = w*16+g and r1 = r0+8; cols {8nt+2q, 8nt+2q+1}
    float mx0 = -1e30f, mx1 = -1e30f;
#pragma unroll
    for (int nt = 0; nt < 32; ++nt) {
        mx0 = fmaxf(mx0, fmaxf(acc[nt][0], acc[nt][1]));
        mx1 = fmaxf(mx1, fmaxf(acc[nt][2], acc[nt][3]));
    }
#pragma unroll
    for (int o = 1; o <= 2; o <<= 1) {
        mx0 = fmaxf(mx0, __shfl_xor_sync(0xffffffffu, mx0, o));
        mx1 = fmaxf(mx1, __shfl_xor_sync(0xffffffffu, mx1, o));
    }
    float s0 = 0.f, s1 = 0.f;
#pragma unroll
    for (int nt = 0; nt < 32; ++nt) {
        acc[nt][0] = __expf(acc[nt][0] - mx0);
        acc[nt][1] = __expf(acc[nt][1] - mx0);
        acc[nt][2] = __expf(acc[nt][2] - mx1);
        acc[nt][3] = __expf(acc[nt][3] - mx1);
        s0 += acc[nt][0] + acc[nt][1];
        s1 += acc[nt][2] + acc[nt][3];
    }
#pragma unroll
    for (int o = 1; o <= 2; o <<= 1) {
        s0 += __shfl_xor_sync(0xffffffffu, s0, o);
        s1 += __shfl_xor_sync(0xffffffffu, s1, o);
    }
    float r0s = 1.f / s0, r1s = 1.f / s1;
    int row0 = w * 16 + g, row1 = row0 + 8;
#pragma unroll
    for (int nt = 0; nt < 32; ++nt) {
        *reinterpret_cast<uint32_t*>(Psm + row0 * SP + nt * 8 + 2 * q) =
            pack_bf16x2(acc[nt][0] * r0s, acc[nt][1] * r0s);
        *reinterpret_cast<uint32_t*>(Psm + row1 * SP + nt * 8 + 2 * q) =
            pack_bf16x2(acc[nt][2] * r1s, acc[nt][3] * r1s);
    }
    __syncthreads();

    // ---------- Phase 3: out[128][768] = prob @ PWT^T (+bias) ----------
    const int wm = w & 1;        // 2 M-groups of 64 rows
    const int wn = w >> 1;       // 4 N-groups of 32 cols
    for (int ch = 0; ch < 6; ++ch) {
        int e0 = ch * 128;
        // stage PWT rows [e0, e0+128) x 256 bf16 = 4096 uint4, 32 per row
#pragma unroll
        for (int it = 0; it < 16; ++it) {
            int idx = tid + 256 * it;        // 0..4095
            int row = idx >> 5;              // 0..127
            int c   = idx & 31;              // 32 uint4 per row (256 bf16)
            uint4 v = *reinterpret_cast<const uint4*>(g_pwt + (e0 + row) * KP + c * 8);
            *reinterpret_cast<uint4*>(PWs + row * SW + c * 8) = v;
        }
        __syncthreads();

        float acc2[4][4][4];
#pragma unroll
        for (int mt = 0; mt < 4; ++mt)
#pragma unroll
            for (int nt = 0; nt < 4; ++nt)
#pragma unroll
                for (int j = 0; j < 4; ++j) acc2[mt][nt][j] = 0.f;

#pragma unroll
        for (int ks = 0; ks < 16; ++ks) {
            int kb = ks * 16;
            uint32_t af[4][4];
#pragma unroll
            for (int mt = 0; mt < 4; ++mt) {
                const __nv_bfloat16* Ab = Psm + (wm * 64 + mt * 16 + g) * SP + kb + 2 * q;
                af[mt][0] = *reinterpret_cast<const uint32_t*>(Ab);
                af[mt][1] = *reinterpret_cast<const uint32_t*>(Ab + 8 * SP);
                af[mt][2] = *reinterpret_cast<const uint32_t*>(Ab + 8);
                af[mt][3] = *reinterpret_cast<const uint32_t*>(Ab + 8 * SP + 8);
            }
#pragma unroll
            for (int nt = 0; nt < 4; ++nt) {
                const __nv_bfloat16* Bb = PWs + (wn * 32 + nt * 8 + g) * SW + kb + 2 * q;
                uint32_t b0 = *reinterpret_cast<const uint32_t*>(Bb);
                uint32_t b1 = *reinterpret_cast<const uint32_t*>(Bb + 8);
#pragma unroll
                for (int mt = 0; mt < 4; ++mt)
                    mma_bf16(acc2[mt][nt][0], acc2[mt][nt][1], acc2[mt][nt][2], acc2[mt][nt][3],
                             af[mt][0], af[mt][1], af[mt][2], af[mt][3], b0, b1);
            }
        }
        // epilogue
#pragma unroll
        for (int nt = 0; nt < 4; ++nt) {
            int cc = e0 + wn * 32 + nt * 8 + 2 * q;
            float b0v = bias[cc];
            float b1v = bias[cc + 1];
#pragma unroll
            for (int mt = 0; mt < 4; ++mt) {
                long r0g = m0 + wm * 64 + mt * 16 + g;
                *reinterpret_cast<float2*>(out + r0g * D + cc) =
                    make_float2(acc2[mt][nt][0] + b0v, acc2[mt][nt][1] + b1v);
                *reinterpret_cast<float2*>(out + (r0g + 8) * D + cc) =
                    make_float2(acc2[mt][nt][2] + b0v, acc2[mt][nt][3] + b1v);
            }
        }
        __syncthreads();
    }
}

// ---------------------------------------------------------------------------
extern "C" void kernel_launch(void* const* d_in, const int* in_sizes, int n_in,
                              void* d_out, int out_size) {
    const float* x = (const float*)d_in[0];
    const float* P = (const float*)d_in[1];
    const float* W = (const float*)d_in[2];
    const float* b = (const float*)d_in[3];
    float* out = (float*)d_out;

    cudaFuncSetAttribute(main_kernel, cudaFuncAttributeMaxDynamicSharedMemorySize, SMEM_MAIN);

    pn_kernel<<<KP, 256>>>(P);
    pwt_kernel<<<D / 4, 256>>>(P, W);

    int rows = in_sizes[0] / D;               // B*N = 131072
    main_kernel<<<rows / M_TILE, 256, SMEM_MAIN>>>(x, b, out);
}

// round 5
// speedup vs baseline: 1.2947x; 1.2947x over previous
#include <cuda_runtime.h>
#include <cuda_bf16.h>
#include <cstdint>

#define D  768
#define KP 256

__device__ __align__(16) __nv_bfloat16 g_pn[KP * D];    // normalized prototypes [k][d]
__device__ __align__(16) __nv_bfloat16 g_pwt[D * KP];   // (P @ W^T / K) : [e][k]

// ---------------------------------------------------------------------------
__device__ __forceinline__ uint32_t smem_u32(const void* p) {
    uint32_t a;
    asm("{ .reg .u64 t; cvta.to.shared.u64 t, %1; cvt.u32.u64 %0, t; }" : "=r"(a) : "l"(p));
    return a;
}
__device__ __forceinline__ uint32_t packbf(float lo, float hi) {
    __nv_bfloat162 h = __float22bfloat162_rn(make_float2(lo, hi));
    return *reinterpret_cast<uint32_t*>(&h);
}
__device__ __forceinline__ void ldsm_x4(uint32_t& r0, uint32_t& r1, uint32_t& r2, uint32_t& r3,
                                        uint32_t addr) {
    asm volatile("ldmatrix.sync.aligned.m8n8.x4.shared.b16 {%0,%1,%2,%3}, [%4];"
                 : "=r"(r0), "=r"(r1), "=r"(r2), "=r"(r3) : "r"(addr));
}
__device__ __forceinline__ void mma4(float* c, uint32_t a0, uint32_t a1, uint32_t a2, uint32_t a3,
                                     uint32_t b0, uint32_t b1) {
    asm volatile(
        "mma.sync.aligned.m16n8k16.row.col.f32.bf16.bf16.f32 "
        "{%0,%1,%2,%3}, {%4,%5,%6,%7}, {%8,%9}, {%0,%1,%2,%3};"
        : "+f"(c[0]), "+f"(c[1]), "+f"(c[2]), "+f"(c[3])
        : "r"(a0), "r"(a1), "r"(a2), "r"(a3), "r"(b0), "r"(b1));
}
#define CP16(dst, src) asm volatile("cp.async.cg.shared.global [%0], [%1], 16;" :: "r"(dst), "l"(src))
#define CP_COMMIT()    asm volatile("cp.async.commit_group;" ::: "memory")
#define CP_WAIT0()     asm volatile("cp.async.wait_group 0;" ::: "memory")

// ---------------------------------------------------------------------------
// Prep kernel 1: normalize prototypes -> bf16
// ---------------------------------------------------------------------------
__global__ void pn_kernel(const float* __restrict__ P) {
    __shared__ float red[8];
    int k = blockIdx.x;
    const float* row = P + k * D;
    float s = 0.f;
    for (int d = threadIdx.x; d < D; d += 256) { float v = row[d]; s += v * v; }
#pragma unroll
    for (int o = 16; o; o >>= 1) s += __shfl_xor_sync(0xffffffffu, s, o);
    if ((threadIdx.x & 31) == 0) red[threadIdx.x >> 5] = s;
    __syncthreads();
    if (threadIdx.x == 0) {
        float t = 0.f;
#pragma unroll
        for (int i = 0; i < 8; ++i) t += red[i];
        red[0] = 1.f / fmaxf(sqrtf(t), 1e-12f);
    }
    __syncthreads();
    float iv = red[0];
    for (int d = threadIdx.x; d < D; d += 256)
        g_pn[k * D + d] = __float2bfloat16(row[d] * iv);
}

// ---------------------------------------------------------------------------
// Prep kernel 2: PWT[e][k] = (1/K) * sum_d P[k][d] * W[e][d]
// ---------------------------------------------------------------------------
__global__ void pwt_kernel(const float* __restrict__ P, const float* __restrict__ W) {
    __shared__ float Pt[256 * 33];
    __shared__ float Wt[4 * 33];
    int e0 = blockIdx.x * 4;
    int k  = threadIdx.x;
    float a0 = 0.f, a1 = 0.f, a2 = 0.f, a3 = 0.f;
    for (int dc = 0; dc < D; dc += 32) {
#pragma unroll
        for (int it = 0; it < 32; ++it) {
            int idx = threadIdx.x + 256 * it;
            int row = idx >> 5, d = idx & 31;
            Pt[row * 33 + d] = P[row * D + dc + d];
        }
        if (threadIdx.x < 128) {
            int e = threadIdx.x >> 5, d = threadIdx.x & 31;
            Wt[e * 33 + d] = W[(e0 + e) * D + dc + d];
        }
        __syncthreads();
#pragma unroll
        for (int d = 0; d < 32; ++d) {
            float p = Pt[k * 33 + d];
            a0 += p * Wt[0 * 33 + d];
            a1 += p * Wt[1 * 33 + d];
            a2 += p * Wt[2 * 33 + d];
            a3 += p * Wt[3 * 33 + d];
        }
        __syncthreads();
    }
    const float sc = 1.f / 256.f;
    g_pwt[(e0 + 0) * KP + k] = __float2bfloat16(a0 * sc);
    g_pwt[(e0 + 1) * KP + k] = __float2bfloat16(a1 * sc);
    g_pwt[(e0 + 2) * KP + k] = __float2bfloat16(a2 * sc);
    g_pwt[(e0 + 3) * KP + k] = __float2bfloat16(a3 * sc);
}

// ---------------------------------------------------------------------------
// Main fused kernel (mma.sync + ldmatrix + cp.async pipelines)
// ---------------------------------------------------------------------------
// smem byte map:
#define OFF_INV   0          // float[128]  (1/||x_row||)
#define OFF_INVS  512        // float[128]  (1/row exp-sum)
#define OFF_PARTS 1024       // float[8][128] partial exp sums
#define OFF_EXP   5120       // bf16 [128][264] (stride 528B)  -> 67584
#define OFF_PW0   72704      // bf16 [128][264]
#define OFF_PW1   140288
#define SMEM_MAIN 207872
// phase-1 overlays (inside the PW region):
#define OFF_XB0   72704              // bf16 [128][72] (stride 144B)
#define OFF_XB1   (72704 + 18432)
#define OFF_PN0   (72704 + 36864)    // bf16 [256][72]
#define OFF_PN1   (72704 + 73728)

__global__ __launch_bounds__(256, 1)
void main_kernel(const float* __restrict__ x, const float* __restrict__ bias,
                 float* __restrict__ out) {
    extern __shared__ char smem[];
    const uint32_t sb = smem_u32(smem);
    const int tid = threadIdx.x, w = tid >> 5, lane = tid & 31;
    const int g = lane >> 2, q = lane & 3;
    const long m0 = (long)blockIdx.x * 128;

    float* inv   = reinterpret_cast<float*>(smem + OFF_INV);
    float* invS  = reinterpret_cast<float*>(smem + OFF_INVS);
    float* parts = reinterpret_cast<float*>(smem + OFF_PARTS);

    // ---- per-thread constant offsets ----
    // x staging: thread covers rows (tid>>4)+16f, cols (tid&15)*4..+4 of each 64-col chunk
    const int xr0 = tid >> 4, xc4 = tid & 15;
    const float* xbase = x + (m0 + xr0) * D + xc4 * 4;      // + f*16*D + c*64
    // A ldmatrix lane offset (stride 144)
    const uint32_t aoff1 = ((lane & 7) + ((lane >> 3) & 1) * 8) * 144 + ((lane >> 4) & 1) * 16;
    // B ldmatrix lane offset (stride 144), + warp col base
    const uint32_t boff1 = (w * 32 + (lane & 7) + ((lane >> 4) & 1) * 8) * 144 + ((lane >> 3) & 1) * 16;
    // pn cp.async: thread row base tid>>3 (+32it), 16B unit tid&7
    const int pnr = tid >> 3, pnu = tid & 7;

    float acc[8][4][4];
#pragma unroll
    for (int mt = 0; mt < 8; ++mt)
#pragma unroll
        for (int nt = 0; nt < 4; ++nt)
#pragma unroll
            for (int j = 0; j < 4; ++j) acc[mt][nt][j] = 0.f;

    float sq[8];
#pragma unroll
    for (int f = 0; f < 8; ++f) sq[f] = 0.f;

    // ---- prologue: load x chunk 0, cp.async pn chunk 0 ----
    float4 R[8];
#pragma unroll
    for (int f = 0; f < 8; ++f)
        R[f] = *reinterpret_cast<const float4*>(xbase + f * 16 * D);
    {
        const char* src = reinterpret_cast<const char*>(g_pn) + pnr * (D * 2) + pnu * 16;
#pragma unroll
        for (int it = 0; it < 8; ++it)
            CP16(sb + OFF_PN0 + (pnr + 32 * it) * 144 + pnu * 16, src + it * 32 * (D * 2));
        CP_COMMIT();
    }

    // ---- Phase 1: sim = x @ pn^T  (12 K-chunks of 64) ----
    for (int c = 0; c < 12; ++c) {
        const int b = c & 1;
        const uint32_t XB = b ? (sb + OFF_XB1) : (sb + OFF_XB0);
        const uint32_t PN = b ? (sb + OFF_PN1) : (sb + OFF_PN0);
        // convert prefetched x -> bf16 smem, accumulate sumsq
#pragma unroll
        for (int f = 0; f < 8; ++f) {
            float4 v = R[f];
            sq[f] += v.x * v.x + v.y * v.y + v.z * v.z + v.w * v.w;
            uint2 p = make_uint2(packbf(v.x, v.y), packbf(v.z, v.w));
            *reinterpret_cast<uint2*>(smem + (XB - sb) + (xr0 + 16 * f) * 144 + xc4 * 8) = p;
        }
        if (c == 11) {
            // reduce sumsq over the 16 threads sharing each row (half-warp)
#pragma unroll
            for (int f = 0; f < 8; ++f) {
                float s = sq[f];
                s += __shfl_xor_sync(0xffffffffu, s, 1);
                s += __shfl_xor_sync(0xffffffffu, s, 2);
                s += __shfl_xor_sync(0xffffffffu, s, 4);
                s += __shfl_xor_sync(0xffffffffu, s, 8);
                if ((tid & 15) == 0) inv[xr0 + 16 * f] = 1.f / fmaxf(sqrtf(s), 1e-12f);
            }
        }
        CP_WAIT0();
        __syncthreads();
        if (c < 11) {
            // prefetch next x chunk + pn chunk
#pragma unroll
            for (int f = 0; f < 8; ++f)
                R[f] = *reinterpret_cast<const float4*>(xbase + f * 16 * D + (c + 1) * 64);
            const uint32_t PNn = b ? (sb + OFF_PN0) : (sb + OFF_PN1);
            const char* src = reinterpret_cast<const char*>(g_pn) + pnr * (D * 2) + (c + 1) * 128 + pnu * 16;
#pragma unroll
            for (int it = 0; it < 8; ++it)
                CP16(PNn + (pnr + 32 * it) * 144 + pnu * 16, src + it * 32 * (D * 2));
            CP_COMMIT();
        }
        // MMA: warp w computes 128 rows x cols [w*32, w*32+32)
#pragma unroll
        for (int ks = 0; ks < 4; ++ks) {
            uint32_t b0, b1, b2, b3, b4, b5, b6, b7;
            ldsm_x4(b0, b1, b2, b3, PN + boff1 + ks * 32);
            ldsm_x4(b4, b5, b6, b7, PN + boff1 + 16 * 144 + ks * 32);
#pragma unroll
            for (int mt = 0; mt < 8; ++mt) {
                uint32_t a0, a1, a2, a3;
                ldsm_x4(a0, a1, a2, a3, XB + aoff1 + mt * 16 * 144 + ks * 32);
                mma4(acc[mt][0], a0, a1, a2, a3, b0, b1);
                mma4(acc[mt][1], a0, a1, a2, a3, b2, b3);
                mma4(acc[mt][2], a0, a1, a2, a3, b4, b5);
                mma4(acc[mt][3], a0, a1, a2, a3, b6, b7);
            }
        }
    }
    __syncthreads();   // all phase-1 MMAs done before PW0 staging overwrites XB1

    // ---- kick off pwt chunk 0 staging (overlaps softmax) ----
    {
        const char* src = reinterpret_cast<const char*>(g_pwt) + ((tid >> 5) * 512) + lane * 16;
#pragma unroll
        for (int it = 0; it < 16; ++it)
            CP16(sb + OFF_PW0 + ((tid >> 5) + 8 * it) * 528 + lane * 16, src + it * 8 * 512);
        CP_COMMIT();
    }

    // ---- softmax: scale by inv[row], exp, write bf16 exp tile + partial sums ----
#pragma unroll
    for (int mt = 0; mt < 8; ++mt) {
        const int r0 = mt * 16 + g, r1 = r0 + 8;
        const float iv0 = inv[r0], iv1 = inv[r1];
        float s0 = 0.f, s1 = 0.f;
#pragma unroll
        for (int nt = 0; nt < 4; ++nt) {
            float e0 = __expf(acc[mt][nt][0] * iv0);
            float e1 = __expf(acc[mt][nt][1] * iv0);
            float e2 = __expf(acc[mt][nt][2] * iv1);
            float e3 = __expf(acc[mt][nt][3] * iv1);
            const uint32_t cb = (w * 32 + nt * 8 + 2 * q) * 2;
            *reinterpret_cast<uint32_t*>(smem + OFF_EXP + r0 * 528 + cb) = packbf(e0, e1);
            *reinterpret_cast<uint32_t*>(smem + OFF_EXP + r1 * 528 + cb) = packbf(e2, e3);
            s0 += e0 + e1; s1 += e2 + e3;
        }
        s0 += __shfl_xor_sync(0xffffffffu, s0, 1);
        s0 += __shfl_xor_sync(0xffffffffu, s0, 2);
        s1 += __shfl_xor_sync(0xffffffffu, s1, 1);
        s1 += __shfl_xor_sync(0xffffffffu, s1, 2);
        if (q == 0) { parts[w * 128 + r0] = s0; parts[w * 128 + r1] = s1; }
    }
    __syncthreads();
    if (tid < 128) {
        float s = 0.f;
#pragma unroll
        for (int ww = 0; ww < 8; ++ww) s += parts[ww * 128 + tid];
        invS[tid] = 1.f / s;
    }

    // ---- Phase 3: out = exp @ PWT^T (6 N-chunks of 128) ----
    const int wm = w & 1, wn = w >> 1;
    const uint32_t aoff3 = (wm * 64 + (lane & 7) + ((lane >> 3) & 1) * 8) * 528 + ((lane >> 4) & 1) * 16;
    const uint32_t boff3 = (wn * 32 + (lane & 7) + ((lane >> 4) & 1) * 8) * 528 + ((lane >> 3) & 1) * 16;

    for (int j = 0; j < 6; ++j) {
        const int b = j & 1;
        const uint32_t PW = b ? (sb + OFF_PW1) : (sb + OFF_PW0);
        CP_WAIT0();
        __syncthreads();
        if (j + 1 < 6) {
            const uint32_t PWn = b ? (sb + OFF_PW0) : (sb + OFF_PW1);
            const char* src = reinterpret_cast<const char*>(g_pwt) +
                              ((j + 1) * 128 + (tid >> 5)) * 512 + lane * 16;
#pragma unroll
            for (int it = 0; it < 16; ++it)
                CP16(PWn + ((tid >> 5) + 8 * it) * 528 + lane * 16, src + it * 8 * 512);
            CP_COMMIT();
        }
        float acc2[4][4][4];
#pragma unroll
        for (int mt = 0; mt < 4; ++mt)
#pragma unroll
            for (int nt = 0; nt < 4; ++nt)
#pragma unroll
                for (int jj = 0; jj < 4; ++jj) acc2[mt][nt][jj] = 0.f;

#pragma unroll
        for (int ks = 0; ks < 16; ++ks) {
            uint32_t b0, b1, b2, b3, b4, b5, b6, b7;
            ldsm_x4(b0, b1, b2, b3, PW + boff3 + ks * 32);
            ldsm_x4(b4, b5, b6, b7, PW + boff3 + 16 * 528 + ks * 32);
#pragma unroll
            for (int mt = 0; mt < 4; ++mt) {
                uint32_t a0, a1, a2, a3;
                ldsm_x4(a0, a1, a2, a3, sb + OFF_EXP + aoff3 + mt * 16 * 528 + ks * 32);
                mma4(acc2[mt][0], a0, a1, a2, a3, b0, b1);
                mma4(acc2[mt][1], a0, a1, a2, a3, b2, b3);
                mma4(acc2[mt][2], a0, a1, a2, a3, b4, b5);
                mma4(acc2[mt][3], a0, a1, a2, a3, b6, b7);
            }
        }
        // epilogue: divide by row exp-sum, add bias, store
#pragma unroll
        for (int mt = 0; mt < 4; ++mt) {
            const int r0 = wm * 64 + mt * 16 + g, r1 = r0 + 8;
            const float is0 = invS[r0], is1 = invS[r1];
#pragma unroll
            for (int nt = 0; nt < 4; ++nt) {
                const int cc = j * 128 + wn * 32 + nt * 8 + 2 * q;
                const float2 bv = *reinterpret_cast<const float2*>(bias + cc);
                *reinterpret_cast<float2*>(out + (m0 + r0) * D + cc) =
                    make_float2(acc2[mt][nt][0] * is0 + bv.x, acc2[mt][nt][1] * is0 + bv.y);
                *reinterpret_cast<float2*>(out + (m0 + r1) * D + cc) =
                    make_float2(acc2[mt][nt][2] * is1 + bv.x, acc2[mt][nt][3] * is1 + bv.y);
            }
        }
    }
}

// ---------------------------------------------------------------------------
extern "C" void kernel_launch(void* const* d_in, const int* in_sizes, int n_in,
                              void* d_out, int out_size) {
    const float* x = (const float*)d_in[0];
    const float* P = (const float*)d_in[1];
    const float* W = (const float*)d_in[2];
    const float* b = (const float*)d_in[3];
    float* out = (float*)d_out;

    cudaFuncSetAttribute(main_kernel, cudaFuncAttributeMaxDynamicSharedMemorySize, SMEM_MAIN);

    pn_kernel<<<KP, 256>>>(P);
    pwt_kernel<<<D / 4, 256>>>(P, W);

    int rows = in_sizes[0] / D;               // 131072
    main_kernel<<<rows / 128, 256, SMEM_MAIN>>>(x, b, out);
}

// round 6
// speedup vs baseline: 1.3122x; 1.0135x over previous
#include <cuda_runtime.h>
#include <cuda_bf16.h>
#include <cstdint>

#define D  768
#define KP 256

__device__ __align__(16) __nv_bfloat16 g_pn[KP * D];    // normalized prototypes [k][d]
__device__ __align__(16) __nv_bfloat16 g_pwt[D * KP];   // (P @ W^T / K) : [e][k]

// ---------------------------------------------------------------------------
__device__ __forceinline__ uint32_t smem_u32(const void* p) {
    uint32_t a;
    asm("{ .reg .u64 t; cvta.to.shared.u64 t, %1; cvt.u32.u64 %0, t; }" : "=r"(a) : "l"(p));
    return a;
}
__device__ __forceinline__ uint32_t packbf(float lo, float hi) {
    __nv_bfloat162 h = __float22bfloat162_rn(make_float2(lo, hi));
    return *reinterpret_cast<uint32_t*>(&h);
}
__device__ __forceinline__ void ldsm_x4(uint32_t& r0, uint32_t& r1, uint32_t& r2, uint32_t& r3,
                                        uint32_t addr) {
    asm volatile("ldmatrix.sync.aligned.m8n8.x4.shared.b16 {%0,%1,%2,%3}, [%4];"
                 : "=r"(r0), "=r"(r1), "=r"(r2), "=r"(r3) : "r"(addr));
}
__device__ __forceinline__ void mma4(float* c, uint32_t a0, uint32_t a1, uint32_t a2, uint32_t a3,
                                     uint32_t b0, uint32_t b1) {
    asm volatile(
        "mma.sync.aligned.m16n8k16.row.col.f32.bf16.bf16.f32 "
        "{%0,%1,%2,%3}, {%4,%5,%6,%7}, {%8,%9}, {%0,%1,%2,%3};"
        : "+f"(c[0]), "+f"(c[1]), "+f"(c[2]), "+f"(c[3])
        : "r"(a0), "r"(a1), "r"(a2), "r"(a3), "r"(b0), "r"(b1));
}
#define CP16(dst, src) asm volatile("cp.async.cg.shared.global [%0], [%1], 16;" :: "r"(dst), "l"(src))
#define CP_COMMIT()    asm volatile("cp.async.commit_group;" ::: "memory")
#define CP_WAIT0()     asm volatile("cp.async.wait_group 0;" ::: "memory")

// ---------------------------------------------------------------------------
// Merged prep kernel: blocks [0,256) normalize prototypes; [256,448) build PWT
// ---------------------------------------------------------------------------
__global__ void prep_kernel(const float* __restrict__ P, const float* __restrict__ W) {
    __shared__ float Pt[256 * 33 + 8];
    __shared__ float Wt[4 * 33];
    if (blockIdx.x < 256) {
        float* red = Pt;
        int k = blockIdx.x;
        const float* row = P + k * D;
        float s = 0.f;
        for (int d = threadIdx.x; d < D; d += 256) { float v = row[d]; s += v * v; }
#pragma unroll
        for (int o = 16; o; o >>= 1) s += __shfl_xor_sync(0xffffffffu, s, o);
        if ((threadIdx.x & 31) == 0) red[threadIdx.x >> 5] = s;
        __syncthreads();
        if (threadIdx.x == 0) {
            float t = 0.f;
#pragma unroll
            for (int i = 0; i < 8; ++i) t += red[i];
            red[0] = 1.f / fmaxf(sqrtf(t), 1e-12f);
        }
        __syncthreads();
        float iv = red[0];
        for (int d = threadIdx.x; d < D; d += 256)
            g_pn[k * D + d] = __float2bfloat16(row[d] * iv);
    } else {
        int e0 = (blockIdx.x - 256) * 4;
        int k  = threadIdx.x;
        float a0 = 0.f, a1 = 0.f, a2 = 0.f, a3 = 0.f;
        for (int dc = 0; dc < D; dc += 32) {
#pragma unroll
            for (int it = 0; it < 32; ++it) {
                int idx = threadIdx.x + 256 * it;
                int row = idx >> 5, d = idx & 31;
                Pt[row * 33 + d] = P[row * D + dc + d];
            }
            if (threadIdx.x < 128) {
                int e = threadIdx.x >> 5, d = threadIdx.x & 31;
                Wt[e * 33 + d] = W[(e0 + e) * D + dc + d];
            }
            __syncthreads();
#pragma unroll
            for (int d = 0; d < 32; ++d) {
                float p = Pt[k * 33 + d];
                a0 += p * Wt[0 * 33 + d];
                a1 += p * Wt[1 * 33 + d];
                a2 += p * Wt[2 * 33 + d];
                a3 += p * Wt[3 * 33 + d];
            }
            __syncthreads();
        }
        const float sc = 1.f / 256.f;
        g_pwt[(e0 + 0) * KP + k] = __float2bfloat16(a0 * sc);
        g_pwt[(e0 + 1) * KP + k] = __float2bfloat16(a1 * sc);
        g_pwt[(e0 + 2) * KP + k] = __float2bfloat16(a2 * sc);
        g_pwt[(e0 + 3) * KP + k] = __float2bfloat16(a3 * sc);
    }
}

// ---------------------------------------------------------------------------
// Main fused kernel: 512 threads (16 warps), mma.sync + ldmatrix + cp.async
// ---------------------------------------------------------------------------
#define OFF_INV   0          // float[128]
#define OFF_INVS  512        // float[128]
#define OFF_PARTS 1024       // float[8][128] partial exp sums
#define OFF_EXP   5120       // bf16 [128][264] (stride 528B)
#define OFF_PW0   72704      // bf16 [128][264]
#define OFF_PW1   140288
#define SMEM_MAIN 207872
// phase-1 overlays (inside PW region):
#define OFF_XB0   72704              // bf16 [128][72] (stride 144B)
#define OFF_XB1   (72704 + 18432)
#define OFF_PN0   (72704 + 36864)    // bf16 [256][72]
#define OFF_PN1   (72704 + 73728)

__global__ __launch_bounds__(512, 1)
void main_kernel(const float* __restrict__ x, const float* __restrict__ bias,
                 float* __restrict__ out) {
    extern __shared__ char smem[];
    const uint32_t sb = smem_u32(smem);
    const int tid = threadIdx.x, w = tid >> 5, lane = tid & 31;
    const int g = lane >> 2, q = lane & 3;
    const long m0 = (long)blockIdx.x * 128;

    float* inv   = reinterpret_cast<float*>(smem + OFF_INV);
    float* invS  = reinterpret_cast<float*>(smem + OFF_INVS);
    float* parts = reinterpret_cast<float*>(smem + OFF_PARTS);

    // ---- phase-1 warp tiling: wm1 = M half (64 rows), wn1 = N group (32 cols)
    const int wm1 = w & 1, wn1 = w >> 1;
    // x staging: thread covers rows (tid>>4)+32f, col-quad tid&15
    const int xr0 = tid >> 4, xc4 = tid & 15;
    const float* xbase = x + (m0 + xr0) * D + xc4 * 4;
    // ldmatrix lane offsets (stride 144)
    const uint32_t aoff1 = (wm1 * 64 + (lane & 7) + ((lane >> 3) & 1) * 8) * 144 + ((lane >> 4) & 1) * 16;
    const uint32_t boff1 = (wn1 * 32 + (lane & 7) + ((lane >> 4) & 1) * 8) * 144 + ((lane >> 3) & 1) * 16;

    float acc[4][4][4];
#pragma unroll
    for (int mt = 0; mt < 4; ++mt)
#pragma unroll
        for (int nt = 0; nt < 4; ++nt)
#pragma unroll
            for (int j = 0; j < 4; ++j) acc[mt][nt][j] = 0.f;

    float sq[4] = {0.f, 0.f, 0.f, 0.f};

    // ---- prologue: prefetch x chunk 0, cp.async pn chunk 0 ----
    float4 R[4];
#pragma unroll
    for (int f = 0; f < 4; ++f)
        R[f] = *reinterpret_cast<const float4*>(xbase + f * 32 * D);
    {
#pragma unroll
        for (int it = 0; it < 4; ++it) {
            int idx = tid + 512 * it;          // 0..2047
            int row = idx >> 3, u = idx & 7;   // 256 rows x 8 16B units
            CP16(sb + OFF_PN0 + row * 144 + u * 16,
                 reinterpret_cast<const char*>(g_pn) + row * (D * 2) + u * 16);
        }
        CP_COMMIT();
    }

    // ---- Phase 1: sim = x @ pn^T (12 K-chunks of 64) ----
    for (int c = 0; c < 12; ++c) {
        const int b = c & 1;
        const uint32_t XB = b ? (sb + OFF_XB1) : (sb + OFF_XB0);
        const uint32_t PN = b ? (sb + OFF_PN1) : (sb + OFF_PN0);
        // convert prefetched x -> bf16 smem, accumulate sumsq
#pragma unroll
        for (int f = 0; f < 4; ++f) {
            float4 v = R[f];
            sq[f] += v.x * v.x + v.y * v.y + v.z * v.z + v.w * v.w;
            uint2 p = make_uint2(packbf(v.x, v.y), packbf(v.z, v.w));
            *reinterpret_cast<uint2*>(smem + (XB - sb) + (xr0 + 32 * f) * 144 + xc4 * 8) = p;
        }
        if (c == 11) {
#pragma unroll
            for (int f = 0; f < 4; ++f) {
                float s = sq[f];
                s += __shfl_xor_sync(0xffffffffu, s, 1);
                s += __shfl_xor_sync(0xffffffffu, s, 2);
                s += __shfl_xor_sync(0xffffffffu, s, 4);
                s += __shfl_xor_sync(0xffffffffu, s, 8);
                if ((tid & 15) == 0) inv[xr0 + 32 * f] = 1.f / fmaxf(sqrtf(s), 1e-12f);
            }
        }
        CP_WAIT0();
        __syncthreads();
        if (c < 11) {
#pragma unroll
            for (int f = 0; f < 4; ++f)
                R[f] = *reinterpret_cast<const float4*>(xbase + f * 32 * D + (c + 1) * 64);
            const uint32_t PNn = b ? (sb + OFF_PN0) : (sb + OFF_PN1);
#pragma unroll
            for (int it = 0; it < 4; ++it) {
                int idx = tid + 512 * it;
                int row = idx >> 3, u = idx & 7;
                CP16(PNn + row * 144 + u * 16,
                     reinterpret_cast<const char*>(g_pn) + row * (D * 2) + (c + 1) * 128 + u * 16);
            }
            CP_COMMIT();
        }
        // MMA: warp computes rows [wm1*64, +64) x cols [wn1*32, +32)
#pragma unroll
        for (int ks = 0; ks < 4; ++ks) {
            uint32_t b0, b1, b2, b3, b4, b5, b6, b7;
            ldsm_x4(b0, b1, b2, b3, PN + boff1 + ks * 32);
            ldsm_x4(b4, b5, b6, b7, PN + boff1 + 16 * 144 + ks * 32);
#pragma unroll
            for (int mt = 0; mt < 4; ++mt) {
                uint32_t a0, a1, a2, a3;
                ldsm_x4(a0, a1, a2, a3, XB + aoff1 + mt * 16 * 144 + ks * 32);
                mma4(acc[mt][0], a0, a1, a2, a3, b0, b1);
                mma4(acc[mt][1], a0, a1, a2, a3, b2, b3);
                mma4(acc[mt][2], a0, a1, a2, a3, b4, b5);
                mma4(acc[mt][3], a0, a1, a2, a3, b6, b7);
            }
        }
    }
    __syncthreads();   // phase-1 MMAs done before PW0 staging overwrites overlay

    // ---- kick off pwt chunk 0 staging (overlaps softmax) ----
    {
#pragma unroll
        for (int it = 0; it < 8; ++it) {
            int idx = tid + 512 * it;           // 0..4095 16B units
            int row = idx >> 5, u = idx & 31;   // 128 rows x 32 units
            CP16(sb + OFF_PW0 + row * 528 + u * 16,
                 reinterpret_cast<const char*>(g_pwt) + row * 512 + u * 16);
        }
        CP_COMMIT();
    }

    // ---- softmax: scale by inv[row], exp, write bf16 exp tile + partial sums ----
#pragma unroll
    for (int mt = 0; mt < 4; ++mt) {
        const int r0 = wm1 * 64 + mt * 16 + g, r1 = r0 + 8;
        const float iv0 = inv[r0], iv1 = inv[r1];
        float s0 = 0.f, s1 = 0.f;
#pragma unroll
        for (int nt = 0; nt < 4; ++nt) {
            float e0 = __expf(acc[mt][nt][0] * iv0);
            float e1 = __expf(acc[mt][nt][1] * iv0);
            float e2 = __expf(acc[mt][nt][2] * iv1);
            float e3 = __expf(acc[mt][nt][3] * iv1);
            const uint32_t cb = (wn1 * 32 + nt * 8 + 2 * q) * 2;
            *reinterpret_cast<uint32_t*>(smem + OFF_EXP + r0 * 528 + cb) = packbf(e0, e1);
            *reinterpret_cast<uint32_t*>(smem + OFF_EXP + r1 * 528 + cb) = packbf(e2, e3);
            s0 += e0 + e1; s1 += e2 + e3;
        }
        s0 += __shfl_xor_sync(0xffffffffu, s0, 1);
        s0 += __shfl_xor_sync(0xffffffffu, s0, 2);
        s1 += __shfl_xor_sync(0xffffffffu, s1, 1);
        s1 += __shfl_xor_sync(0xffffffffu, s1, 2);
        if (q == 0) { parts[wn1 * 128 + r0] = s0; parts[wn1 * 128 + r1] = s1; }
    }
    __syncthreads();
    if (tid < 128) {
        float s = 0.f;
#pragma unroll
        for (int ww = 0; ww < 8; ++ww) s += parts[ww * 128 + tid];
        invS[tid] = 1.f / s;
    }

    // ---- Phase 3: out = exp @ PWT^T (6 N-chunks of 128) ----
    const int wm3 = w & 3, wn3 = w >> 2;      // 4 M groups x 4 N groups (32x32/warp)
    const uint32_t aoff3 = (wm3 * 32 + (lane & 7) + ((lane >> 3) & 1) * 8) * 528 + ((lane >> 4) & 1) * 16;
    const uint32_t boff3 = (wn3 * 32 + (lane & 7) + ((lane >> 4) & 1) * 8) * 528 + ((lane >> 3) & 1) * 16;

    for (int j = 0; j < 6; ++j) {
        const int b = j & 1;
        const uint32_t PW = b ? (sb + OFF_PW1) : (sb + OFF_PW0);
        CP_WAIT0();
        __syncthreads();
        if (j + 1 < 6) {
            const uint32_t PWn = b ? (sb + OFF_PW0) : (sb + OFF_PW1);
#pragma unroll
            for (int it = 0; it < 8; ++it) {
                int idx = tid + 512 * it;
                int row = idx >> 5, u = idx & 31;
                CP16(PWn + row * 528 + u * 16,
                     reinterpret_cast<const char*>(g_pwt) + ((j + 1) * 128 + row) * 512 + u * 16);
            }
            CP_COMMIT();
        }
        float acc2[2][4][4];
#pragma unroll
        for (int mt = 0; mt < 2; ++mt)
#pragma unroll
            for (int nt = 0; nt < 4; ++nt)
#pragma unroll
                for (int jj = 0; jj < 4; ++jj) acc2[mt][nt][jj] = 0.f;

#pragma unroll
        for (int ks = 0; ks < 16; ++ks) {
            uint32_t b0, b1, b2, b3, b4, b5, b6, b7;
            ldsm_x4(b0, b1, b2, b3, PW + boff3 + ks * 32);
            ldsm_x4(b4, b5, b6, b7, PW + boff3 + 16 * 528 + ks * 32);
#pragma unroll
            for (int mt = 0; mt < 2; ++mt) {
                uint32_t a0, a1, a2, a3;
                ldsm_x4(a0, a1, a2, a3, sb + OFF_EXP + aoff3 + mt * 16 * 528 + ks * 32);
                mma4(acc2[mt][0], a0, a1, a2, a3, b0, b1);
                mma4(acc2[mt][1], a0, a1, a2, a3, b2, b3);
                mma4(acc2[mt][2], a0, a1, a2, a3, b4, b5);
                mma4(acc2[mt][3], a0, a1, a2, a3, b6, b7);
            }
        }
        // epilogue: divide by row exp-sum, add bias, store
#pragma unroll
        for (int mt = 0; mt < 2; ++mt) {
            const int r0 = wm3 * 32 + mt * 16 + g, r1 = r0 + 8;
            const float is0 = invS[r0], is1 = invS[r1];
#pragma unroll
            for (int nt = 0; nt < 4; ++nt) {
                const int cc = j * 128 + wn3 * 32 + nt * 8 + 2 * q;
                const float2 bv = *reinterpret_cast<const float2*>(bias + cc);
                *reinterpret_cast<float2*>(out + (m0 + r0) * D + cc) =
                    make_float2(acc2[mt][nt][0] * is0 + bv.x, acc2[mt][nt][1] * is0 + bv.y);
                *reinterpret_cast<float2*>(out + (m0 + r1) * D + cc) =
                    make_float2(acc2[mt][nt][2] * is1 + bv.x, acc2[mt][nt][3] * is1 + bv.y);
            }
        }
    }
}

// ---------------------------------------------------------------------------
extern "C" void kernel_launch(void* const* d_in, const int* in_sizes, int n_in,
                              void* d_out, int out_size) {
    const float* x = (const float*)d_in[0];
    const float* P = (const float*)d_in[1];
    const float* W = (const float*)d_in[2];
    const float* b = (const float*)d_in[3];
    float* out = (float*)d_out;

    cudaFuncSetAttribute(main_kernel, cudaFuncAttributeMaxDynamicSharedMemorySize, SMEM_MAIN);

    prep_kernel<<<448, 256>>>(P, W);

    int rows = in_sizes[0] / D;               // 131072
    main_kernel<<<rows / 128, 512, SMEM_MAIN>>>(x, b, out);
}

// round 7
// speedup vs baseline: 1.3424x; 1.0230x over previous
#include <cuda_runtime.h>
#include <cuda_bf16.h>
#include <cstdint>

#define D  768
#define KP 256

__device__ __align__(16) __nv_bfloat16 g_pn[KP * D];    // normalized prototypes [k][d]
__device__ __align__(16) __nv_bfloat16 g_pwt[D * KP];   // (P @ W^T / K) : [e][k]

// ---------------------------------------------------------------------------
__device__ __forceinline__ uint32_t smem_u32(const void* p) {
    uint32_t a;
    asm("{ .reg .u64 t; cvta.to.shared.u64 t, %1; cvt.u32.u64 %0, t; }" : "=r"(a) : "l"(p));
    return a;
}
__device__ __forceinline__ uint32_t packbf(float lo, float hi) {
    __nv_bfloat162 h = __float22bfloat162_rn(make_float2(lo, hi));
    return *reinterpret_cast<uint32_t*>(&h);
}
__device__ __forceinline__ void ldsm_x4(uint32_t& r0, uint32_t& r1, uint32_t& r2, uint32_t& r3,
                                        uint32_t addr) {
    asm volatile("ldmatrix.sync.aligned.m8n8.x4.shared.b16 {%0,%1,%2,%3}, [%4];"
                 : "=r"(r0), "=r"(r1), "=r"(r2), "=r"(r3) : "r"(addr));
}
__device__ __forceinline__ void mma4(float* c, uint32_t a0, uint32_t a1, uint32_t a2, uint32_t a3,
                                     uint32_t b0, uint32_t b1) {
    asm volatile(
        "mma.sync.aligned.m16n8k16.row.col.f32.bf16.bf16.f32 "
        "{%0,%1,%2,%3}, {%4,%5,%6,%7}, {%8,%9}, {%0,%1,%2,%3};"
        : "+f"(c[0]), "+f"(c[1]), "+f"(c[2]), "+f"(c[3])
        : "r"(a0), "r"(a1), "r"(a2), "r"(a3), "r"(b0), "r"(b1));
}
#define CP16(dst, src) asm volatile("cp.async.cg.shared.global [%0], [%1], 16;" :: "r"(dst), "l"(src))
#define CP_COMMIT()    asm volatile("cp.async.commit_group;" ::: "memory")
#define CP_WAIT0()     asm volatile("cp.async.wait_group 0;" ::: "memory")

// ---------------------------------------------------------------------------
// Merged prep kernel: blocks [0,256) normalize prototypes; [256,448) build PWT
// ---------------------------------------------------------------------------
__global__ void prep_kernel(const float* __restrict__ P, const float* __restrict__ W) {
    __shared__ float Pt[256 * 33 + 8];
    __shared__ float Wt[4 * 33];
    if (blockIdx.x < 256) {
        float* red = Pt;
        int k = blockIdx.x;
        const float* row = P + k * D;
        float s = 0.f;
        for (int d = threadIdx.x; d < D; d += 256) { float v = row[d]; s += v * v; }
#pragma unroll
        for (int o = 16; o; o >>= 1) s += __shfl_xor_sync(0xffffffffu, s, o);
        if ((threadIdx.x & 31) == 0) red[threadIdx.x >> 5] = s;
        __syncthreads();
        if (threadIdx.x == 0) {
            float t = 0.f;
#pragma unroll
            for (int i = 0; i < 8; ++i) t += red[i];
            red[0] = 1.f / fmaxf(sqrtf(t), 1e-12f);
        }
        __syncthreads();
        float iv = red[0];
        for (int d = threadIdx.x; d < D; d += 256)
            g_pn[k * D + d] = __float2bfloat16(row[d] * iv);
    } else {
        int e0 = (blockIdx.x - 256) * 4;
        int k  = threadIdx.x;
        float a0 = 0.f, a1 = 0.f, a2 = 0.f, a3 = 0.f;
        for (int dc = 0; dc < D; dc += 32) {
#pragma unroll
            for (int it = 0; it < 32; ++it) {
                int idx = threadIdx.x + 256 * it;
                int row = idx >> 5, d = idx & 31;
                Pt[row * 33 + d] = P[row * D + dc + d];
            }
            if (threadIdx.x < 128) {
                int e = threadIdx.x >> 5, d = threadIdx.x & 31;
                Wt[e * 33 + d] = W[(e0 + e) * D + dc + d];
            }
            __syncthreads();
#pragma unroll
            for (int d = 0; d < 32; ++d) {
                float p = Pt[k * 33 + d];
                a0 += p * Wt[0 * 33 + d];
                a1 += p * Wt[1 * 33 + d];
                a2 += p * Wt[2 * 33 + d];
                a3 += p * Wt[3 * 33 + d];
            }
            __syncthreads();
        }
        const float sc = 1.f / 256.f;
        g_pwt[(e0 + 0) * KP + k] = __float2bfloat16(a0 * sc);
        g_pwt[(e0 + 1) * KP + k] = __float2bfloat16(a1 * sc);
        g_pwt[(e0 + 2) * KP + k] = __float2bfloat16(a2 * sc);
        g_pwt[(e0 + 3) * KP + k] = __float2bfloat16(a3 * sc);
    }
}

// ---------------------------------------------------------------------------
// Main fused kernel: M_TILE=64, 256 threads, 2 CTAs/SM
// ---------------------------------------------------------------------------
#define OFF_INV   0            // float[64]
#define OFF_INVS  256          // float[64]
#define OFF_PARTS 512          // float[4][64]
#define OFF_EXP   1536         // bf16 [64][264]  (stride 528B) = 33792
#define OFF_PW    35328        // bf16 [128][264] (stride 528B) = 67584
#define SMEM_MAIN 102912
// phase-1 overlays (inside EXP+PW region):
#define OFF_XB0   1536                 // bf16 [64][72]  (stride 144B) = 9216
#define OFF_XB1   (1536 + 9216)
#define OFF_PN0   (1536 + 18432)       // bf16 [256][72] = 36864
#define OFF_PN1   (1536 + 55296)

__global__ __launch_bounds__(256, 2)
void main_kernel(const float* __restrict__ x, const float* __restrict__ bias,
                 float* __restrict__ out) {
    extern __shared__ char smem[];
    const uint32_t sb = smem_u32(smem);
    const int tid = threadIdx.x, w = tid >> 5, lane = tid & 31;
    const int g = lane >> 2, q = lane & 3;
    const long m0 = (long)blockIdx.x * 64;

    float* inv   = reinterpret_cast<float*>(smem + OFF_INV);
    float* invS  = reinterpret_cast<float*>(smem + OFF_INVS);
    float* parts = reinterpret_cast<float*>(smem + OFF_PARTS);

    // ---- phase-1 tiling: wm1 = M half (32 rows), wn1 = N group (64 cols) ----
    const int wm1 = w & 1, wn1 = w >> 1;
    // x staging: thread covers rows (tid>>4)+16f (f=0..3), col-quad tid&15
    const int xr0 = tid >> 4, xc4 = tid & 15;
    const float* xbase = x + (m0 + xr0) * D + xc4 * 4;
    const uint32_t aoff1 = (wm1 * 32 + (lane & 7) + ((lane >> 3) & 1) * 8) * 144 + ((lane >> 4) & 1) * 16;
    const uint32_t boff1 = (wn1 * 64 + (lane & 7) + ((lane >> 4) & 1) * 8) * 144 + ((lane >> 3) & 1) * 16;

    float acc[2][8][4];
#pragma unroll
    for (int mt = 0; mt < 2; ++mt)
#pragma unroll
        for (int nt = 0; nt < 8; ++nt)
#pragma unroll
            for (int j = 0; j < 4; ++j) acc[mt][nt][j] = 0.f;

    float sq[4] = {0.f, 0.f, 0.f, 0.f};

    // ---- prologue: prefetch x chunk 0, cp.async pn chunk 0 ----
    float4 R[4];
#pragma unroll
    for (int f = 0; f < 4; ++f)
        R[f] = *reinterpret_cast<const float4*>(xbase + f * 16 * D);
#pragma unroll
    for (int it = 0; it < 8; ++it) {
        int idx = tid + 256 * it;          // 0..2047
        int row = idx >> 3, u = idx & 7;   // 256 rows x 8 16B units
        CP16(sb + OFF_PN0 + row * 144 + u * 16,
             reinterpret_cast<const char*>(g_pn) + row * (D * 2) + u * 16);
    }
    CP_COMMIT();

    // ---- Phase 1: sim[64][256] = x @ pn^T (12 K-chunks of 64) ----
    for (int c = 0; c < 12; ++c) {
        const int b = c & 1;
        const uint32_t XB = b ? (sb + OFF_XB1) : (sb + OFF_XB0);
        const uint32_t PN = b ? (sb + OFF_PN1) : (sb + OFF_PN0);
        // convert prefetched x -> bf16 smem, accumulate sumsq
#pragma unroll
        for (int f = 0; f < 4; ++f) {
            float4 v = R[f];
            sq[f] += v.x * v.x + v.y * v.y + v.z * v.z + v.w * v.w;
            uint2 p = make_uint2(packbf(v.x, v.y), packbf(v.z, v.w));
            *reinterpret_cast<uint2*>(smem + (XB - sb) + (xr0 + 16 * f) * 144 + xc4 * 8) = p;
        }
        if (c == 11) {
#pragma unroll
            for (int f = 0; f < 4; ++f) {
                float s = sq[f];
                s += __shfl_xor_sync(0xffffffffu, s, 1);
                s += __shfl_xor_sync(0xffffffffu, s, 2);
                s += __shfl_xor_sync(0xffffffffu, s, 4);
                s += __shfl_xor_sync(0xffffffffu, s, 8);
                if ((tid & 15) == 0) inv[xr0 + 16 * f] = 1.f / fmaxf(sqrtf(s), 1e-12f);
            }
        }
        CP_WAIT0();
        __syncthreads();
        if (c < 11) {
#pragma unroll
            for (int f = 0; f < 4; ++f)
                R[f] = *reinterpret_cast<const float4*>(xbase + f * 16 * D + (c + 1) * 64);
            const uint32_t PNn = b ? (sb + OFF_PN0) : (sb + OFF_PN1);
#pragma unroll
            for (int it = 0; it < 8; ++it) {
                int idx = tid + 256 * it;
                int row = idx >> 3, u = idx & 7;
                CP16(PNn + row * 144 + u * 16,
                     reinterpret_cast<const char*>(g_pn) + row * (D * 2) + (c + 1) * 128 + u * 16);
            }
            CP_COMMIT();
        }
        // MMA: warp computes rows [wm1*32,+32) x cols [wn1*64,+64)
#pragma unroll
        for (int ks = 0; ks < 4; ++ks) {
            uint32_t a0[2], a1[2], a2[2], a3[2];
#pragma unroll
            for (int mt = 0; mt < 2; ++mt)
                ldsm_x4(a0[mt], a1[mt], a2[mt], a3[mt], XB + aoff1 + mt * 16 * 144 + ks * 32);
#pragma unroll
            for (int p = 0; p < 4; ++p) {
                uint32_t b0, b1, b2, b3;
                ldsm_x4(b0, b1, b2, b3, PN + boff1 + p * 16 * 144 + ks * 32);
#pragma unroll
                for (int mt = 0; mt < 2; ++mt) {
                    mma4(acc[mt][2 * p],     a0[mt], a1[mt], a2[mt], a3[mt], b0, b1);
                    mma4(acc[mt][2 * p + 1], a0[mt], a1[mt], a2[mt], a3[mt], b2, b3);
                }
            }
        }
    }
    __syncthreads();   // all phase-1 reads done before overlay reuse

    // ---- kick off PW chunk 0 staging (overlaps softmax) ----
#pragma unroll
    for (int it = 0; it < 16; ++it) {
        int idx = tid + 256 * it;           // 0..4095 16B units
        int row = idx >> 5, u = idx & 31;   // 128 rows x 32 units
        CP16(sb + OFF_PW + row * 528 + u * 16,
             reinterpret_cast<const char*>(g_pwt) + row * 512 + u * 16);
    }
    CP_COMMIT();

    // ---- softmax: scale by inv[row], exp, write bf16 exp tile + partial sums ----
#pragma unroll
    for (int mt = 0; mt < 2; ++mt) {
        const int r0 = wm1 * 32 + mt * 16 + g, r1 = r0 + 8;
        const float iv0 = inv[r0], iv1 = inv[r1];
        float s0 = 0.f, s1 = 0.f;
#pragma unroll
        for (int nt = 0; nt < 8; ++nt) {
            float e0 = __expf(acc[mt][nt][0] * iv0);
            float e1 = __expf(acc[mt][nt][1] * iv0);
            float e2 = __expf(acc[mt][nt][2] * iv1);
            float e3 = __expf(acc[mt][nt][3] * iv1);
            const uint32_t cb = (wn1 * 64 + nt * 8 + 2 * q) * 2;
            *reinterpret_cast<uint32_t*>(smem + OFF_EXP + r0 * 528 + cb) = packbf(e0, e1);
            *reinterpret_cast<uint32_t*>(smem + OFF_EXP + r1 * 528 + cb) = packbf(e2, e3);
            s0 += e0 + e1; s1 += e2 + e3;
        }
        s0 += __shfl_xor_sync(0xffffffffu, s0, 1);
        s0 += __shfl_xor_sync(0xffffffffu, s0, 2);
        s1 += __shfl_xor_sync(0xffffffffu, s1, 1);
        s1 += __shfl_xor_sync(0xffffffffu, s1, 2);
        if (q == 0) { parts[wn1 * 64 + r0] = s0; parts[wn1 * 64 + r1] = s1; }
    }
    __syncthreads();
    if (tid < 64) {
        float s = parts[tid] + parts[64 + tid] + parts[128 + tid] + parts[192 + tid];
        invS[tid] = 1.f / s;
    }

    // ---- Phase 3: out[64][768] = exp @ PWT^T (6 e-chunks of 128, single buffer) ----
    const int wm3 = w & 1, wn3 = w >> 1;      // 2 M groups x 4 N groups (32x32/warp)
    const uint32_t aoff3 = (wm3 * 32 + (lane & 7) + ((lane >> 3) & 1) * 8) * 528 + ((lane >> 4) & 1) * 16;
    const uint32_t boff3 = (wn3 * 32 + (lane & 7) + ((lane >> 4) & 1) * 8) * 528 + ((lane >> 3) & 1) * 16;

    for (int j = 0; j < 6; ++j) {
        CP_WAIT0();
        __syncthreads();                      // PW chunk j ready (and invS visible at j=0)

        float acc2[2][4][4];
#pragma unroll
        for (int mt = 0; mt < 2; ++mt)
#pragma unroll
            for (int nt = 0; nt < 4; ++nt)
#pragma unroll
                for (int jj = 0; jj < 4; ++jj) acc2[mt][nt][jj] = 0.f;

#pragma unroll
        for (int ks = 0; ks < 16; ++ks) {
            uint32_t b0, b1, b2, b3, b4, b5, b6, b7;
            ldsm_x4(b0, b1, b2, b3, sb + OFF_PW + boff3 + ks * 32);
            ldsm_x4(b4, b5, b6, b7, sb + OFF_PW + boff3 + 16 * 528 + ks * 32);
#pragma unroll
            for (int mt = 0; mt < 2; ++mt) {
                uint32_t a0, a1, a2, a3;
                ldsm_x4(a0, a1, a2, a3, sb + OFF_EXP + aoff3 + mt * 16 * 528 + ks * 32);
                mma4(acc2[mt][0], a0, a1, a2, a3, b0, b1);
                mma4(acc2[mt][1], a0, a1, a2, a3, b2, b3);
                mma4(acc2[mt][2], a0, a1, a2, a3, b4, b5);
                mma4(acc2[mt][3], a0, a1, a2, a3, b6, b7);
            }
        }
        __syncthreads();                      // all PW reads done
        if (j < 5) {
#pragma unroll
            for (int it = 0; it < 16; ++it) {
                int idx = tid + 256 * it;
                int row = idx >> 5, u = idx & 31;
                CP16(sb + OFF_PW + row * 528 + u * 16,
                     reinterpret_cast<const char*>(g_pwt) + ((j + 1) * 128 + row) * 512 + u * 16);
            }
            CP_COMMIT();
        }
        // epilogue (overlaps next PW load): divide by exp-sum, add bias, store
#pragma unroll
        for (int mt = 0; mt < 2; ++mt) {
            const int r0 = wm3 * 32 + mt * 16 + g, r1 = r0 + 8;
            const float is0 = invS[r0], is1 = invS[r1];
#pragma unroll
            for (int nt = 0; nt < 4; ++nt) {
                const int cc = j * 128 + wn3 * 32 + nt * 8 + 2 * q;
                const float2 bv = *reinterpret_cast<const float2*>(bias + cc);
                *reinterpret_cast<float2*>(out + (m0 + r0) * D + cc) =
                    make_float2(acc2[mt][nt][0] * is0 + bv.x, acc2[mt][nt][1] * is0 + bv.y);
                *reinterpret_cast<float2*>(out + (m0 + r1) * D + cc) =
                    make_float2(acc2[mt][nt][2] * is1 + bv.x, acc2[mt][nt][3] * is1 + bv.y);
            }
        }
    }
}

// ---------------------------------------------------------------------------
extern "C" void kernel_launch(void* const* d_in, const int* in_sizes, int n_in,
                              void* d_out, int out_size) {
    const float* x = (const float*)d_in[0];
    const float* P = (const float*)d_in[1];
    const float* W = (const float*)d_in[2];
    const float* b = (const float*)d_in[3];
    float* out = (float*)d_out;

    cudaFuncSetAttribute(main_kernel, cudaFuncAttributeMaxDynamicSharedMemorySize, SMEM_MAIN);

    prep_kernel<<<448, 256>>>(P, W);

    int rows = in_sizes[0] / D;               // 131072
    main_kernel<<<rows / 64, 256, SMEM_MAIN>>>(x, b, out);
}

// round 8
// speedup vs baseline: 1.3465x; 1.0031x over previous
#include <cuda_runtime.h>
#include <cuda_bf16.h>
#include <cstdint>

#define D  768
#define KP 256

__device__ __align__(16) uint8_t       g_pn8[KP * D];   // normalized prototypes e4m3 [k][d]
__device__ __align__(16) __nv_bfloat16 g_pwt[D * KP];   // (P @ W^T / K) : [e][k]

// ---------------------------------------------------------------------------
__device__ __forceinline__ uint32_t smem_u32(const void* p) {
    uint32_t a;
    asm("{ .reg .u64 t; cvta.to.shared.u64 t, %1; cvt.u32.u64 %0, t; }" : "=r"(a) : "l"(p));
    return a;
}
__device__ __forceinline__ uint32_t packbf(float lo, float hi) {
    __nv_bfloat162 h = __float22bfloat162_rn(make_float2(lo, hi));
    return *reinterpret_cast<uint32_t*>(&h);
}
__device__ __forceinline__ uint16_t packe4m3(float lo, float hi) {
    uint16_t h;
    asm("cvt.rn.satfinite.e4m3x2.f32 %0, %1, %2;" : "=h"(h) : "f"(hi), "f"(lo));
    return h;
}
__device__ __forceinline__ void ldsm_x4(uint32_t& r0, uint32_t& r1, uint32_t& r2, uint32_t& r3,
                                        uint32_t addr) {
    asm volatile("ldmatrix.sync.aligned.m8n8.x4.shared.b16 {%0,%1,%2,%3}, [%4];"
                 : "=r"(r0), "=r"(r1), "=r"(r2), "=r"(r3) : "r"(addr));
}
__device__ __forceinline__ void mma4(float* c, uint32_t a0, uint32_t a1, uint32_t a2, uint32_t a3,
                                     uint32_t b0, uint32_t b1) {
    asm volatile(
        "mma.sync.aligned.m16n8k16.row.col.f32.bf16.bf16.f32 "
        "{%0,%1,%2,%3}, {%4,%5,%6,%7}, {%8,%9}, {%0,%1,%2,%3};"
        : "+f"(c[0]), "+f"(c[1]), "+f"(c[2]), "+f"(c[3])
        : "r"(a0), "r"(a1), "r"(a2), "r"(a3), "r"(b0), "r"(b1));
}
__device__ __forceinline__ void mma8(float* c, uint32_t a0, uint32_t a1, uint32_t a2, uint32_t a3,
                                     uint32_t b0, uint32_t b1) {
    asm volatile(
        "mma.sync.aligned.m16n8k32.row.col.f32.e4m3.e4m3.f32 "
        "{%0,%1,%2,%3}, {%4,%5,%6,%7}, {%8,%9}, {%0,%1,%2,%3};"
        : "+f"(c[0]), "+f"(c[1]), "+f"(c[2]), "+f"(c[3])
        : "r"(a0), "r"(a1), "r"(a2), "r"(a3), "r"(b0), "r"(b1));
}
#define CP16(dst, src) asm volatile("cp.async.cg.shared.global [%0], [%1], 16;" :: "r"(dst), "l"(src))
#define CP_COMMIT()    asm volatile("cp.async.commit_group;" ::: "memory")
#define CP_WAIT0()     asm volatile("cp.async.wait_group 0;" ::: "memory")

// ---------------------------------------------------------------------------
// Merged prep kernel: blocks [0,256) normalize prototypes -> e4m3; rest build PWT
// ---------------------------------------------------------------------------
__global__ void prep_kernel(const float* __restrict__ P, const float* __restrict__ W) {
    __shared__ float Pt[256 * 33 + 8];
    __shared__ float Wt[4 * 33];
    if (blockIdx.x < 256) {
        float* red = Pt;
        int k = blockIdx.x;
        const float* row = P + k * D;
        float s = 0.f;
        for (int d = threadIdx.x; d < D; d += 256) { float v = row[d]; s += v * v; }
#pragma unroll
        for (int o = 16; o; o >>= 1) s += __shfl_xor_sync(0xffffffffu, s, o);
        if ((threadIdx.x & 31) == 0) red[threadIdx.x >> 5] = s;
        __syncthreads();
        if (threadIdx.x == 0) {
            float t = 0.f;
#pragma unroll
            for (int i = 0; i < 8; ++i) t += red[i];
            red[0] = 1.f / fmaxf(sqrtf(t), 1e-12f);
        }
        __syncthreads();
        float iv = red[0];
        for (int p = threadIdx.x; p < D / 2; p += 256) {
            uint16_t h = packe4m3(row[2 * p] * iv, row[2 * p + 1] * iv);
            *reinterpret_cast<uint16_t*>(g_pn8 + k * D + 2 * p) = h;
        }
    } else {
        int e0 = (blockIdx.x - 256) * 4;
        int k  = threadIdx.x;
        float a0 = 0.f, a1 = 0.f, a2 = 0.f, a3 = 0.f;
        for (int dc = 0; dc < D; dc += 32) {
#pragma unroll
            for (int it = 0; it < 32; ++it) {
                int idx = threadIdx.x + 256 * it;
                int row = idx >> 5, d = idx & 31;
                Pt[row * 33 + d] = P[row * D + dc + d];
            }
            if (threadIdx.x < 128) {
                int e = threadIdx.x >> 5, d = threadIdx.x & 31;
                Wt[e * 33 + d] = W[(e0 + e) * D + dc + d];
            }
            __syncthreads();
#pragma unroll
            for (int d = 0; d < 32; ++d) {
                float p = Pt[k * 33 + d];
                a0 += p * Wt[0 * 33 + d];
                a1 += p * Wt[1 * 33 + d];
                a2 += p * Wt[2 * 33 + d];
                a3 += p * Wt[3 * 33 + d];
            }
            __syncthreads();
        }
        const float sc = 1.f / 256.f;
        g_pwt[(e0 + 0) * KP + k] = __float2bfloat16(a0 * sc);
        g_pwt[(e0 + 1) * KP + k] = __float2bfloat16(a1 * sc);
        g_pwt[(e0 + 2) * KP + k] = __float2bfloat16(a2 * sc);
        g_pwt[(e0 + 3) * KP + k] = __float2bfloat16(a3 * sc);
    }
}

// ---------------------------------------------------------------------------
// Main fused kernel: M_TILE=64, 256 threads, 2 CTAs/SM, FP8 GEMM1 + bf16 GEMM2
// ---------------------------------------------------------------------------
#define OFF_INV   0            // float[64]
#define OFF_INVS  256          // float[64]
#define OFF_PARTS 512          // float[4][64]
#define OFF_EXP   1536         // bf16 [64][264]  (stride 528B) = 33792
#define OFF_PW    35328        // bf16 [128][264] (stride 528B) = 67584
#define SMEM_MAIN 102912
// phase-1 overlays (e4m3 tiles, stride 80B = odd 16B units):
#define OFF_XB0   1536                 // e4m3 [64][80]  = 5120
#define OFF_XB1   (1536 + 5120)
#define OFF_PN0   (1536 + 10240)       // e4m3 [256][80] = 20480
#define OFF_PN1   (1536 + 30720)

__global__ __launch_bounds__(256, 2)
void main_kernel(const float* __restrict__ x, const float* __restrict__ bias,
                 float* __restrict__ out) {
    extern __shared__ char smem[];
    const uint32_t sb = smem_u32(smem);
    const int tid = threadIdx.x, w = tid >> 5, lane = tid & 31;
    const int g = lane >> 2, q = lane & 3;
    const long m0 = (long)blockIdx.x * 64;

    float* inv   = reinterpret_cast<float*>(smem + OFF_INV);
    float* invS  = reinterpret_cast<float*>(smem + OFF_INVS);
    float* parts = reinterpret_cast<float*>(smem + OFF_PARTS);

    // ---- phase-1 tiling: wm1 = M half (32 rows), wn1 = N group (64 cols) ----
    const int wm1 = w & 1, wn1 = w >> 1;
    // x staging: thread covers rows (tid>>4)+16f (f=0..3), col-quad tid&15
    const int xr0 = tid >> 4, xc4 = tid & 15;
    const float* xbase = x + (m0 + xr0) * D + xc4 * 4;
    // fp8 ldmatrix offsets (b16 view of e4m3 pairs, row stride 80B)
    const uint32_t aoff1 = (wm1 * 32 + (lane & 7) + ((lane >> 3) & 1) * 8) * 80 + ((lane >> 4) & 1) * 16;
    const uint32_t boff1 = (wn1 * 64 + (lane & 7) + ((lane >> 4) & 1) * 8) * 80 + ((lane >> 3) & 1) * 16;

    float acc[2][8][4];
#pragma unroll
    for (int mt = 0; mt < 2; ++mt)
#pragma unroll
        for (int nt = 0; nt < 8; ++nt)
#pragma unroll
            for (int j = 0; j < 4; ++j) acc[mt][nt][j] = 0.f;

    float sq[4] = {0.f, 0.f, 0.f, 0.f};

    // ---- prologue: prefetch x chunk 0, cp.async pn chunk 0 ----
    float4 R[4];
#pragma unroll
    for (int f = 0; f < 4; ++f)
        R[f] = *reinterpret_cast<const float4*>(xbase + f * 16 * D);
#pragma unroll
    for (int it = 0; it < 4; ++it) {
        int idx = tid + 256 * it;          // 0..1023
        int row = idx >> 2, u = idx & 3;   // 256 rows x 4 16B units (64 e4m3)
        CP16(sb + OFF_PN0 + row * 80 + u * 16, g_pn8 + row * D + u * 16);
    }
    CP_COMMIT();

    // ---- Phase 1 (FP8): sim[64][256] = x @ pn^T (12 K-chunks of 64) ----
    for (int c = 0; c < 12; ++c) {
        const int b = c & 1;
        const uint32_t XB = b ? (sb + OFF_XB1) : (sb + OFF_XB0);
        const uint32_t PN = b ? (sb + OFF_PN1) : (sb + OFF_PN0);
        // convert prefetched x -> e4m3 smem, accumulate sumsq
#pragma unroll
        for (int f = 0; f < 4; ++f) {
            float4 v = R[f];
            sq[f] += v.x * v.x + v.y * v.y + v.z * v.z + v.w * v.w;
            uint32_t word = (uint32_t)packe4m3(v.x, v.y) |
                            ((uint32_t)packe4m3(v.z, v.w) << 16);
            *reinterpret_cast<uint32_t*>(smem + (XB - sb) + (xr0 + 16 * f) * 80 + xc4 * 4) = word;
        }
        if (c == 11) {
#pragma unroll
            for (int f = 0; f < 4; ++f) {
                float s = sq[f];
                s += __shfl_xor_sync(0xffffffffu, s, 1);
                s += __shfl_xor_sync(0xffffffffu, s, 2);
                s += __shfl_xor_sync(0xffffffffu, s, 4);
                s += __shfl_xor_sync(0xffffffffu, s, 8);
                if ((tid & 15) == 0) inv[xr0 + 16 * f] = 1.f / fmaxf(sqrtf(s), 1e-12f);
            }
        }
        CP_WAIT0();
        __syncthreads();
        if (c < 11) {
#pragma unroll
            for (int f = 0; f < 4; ++f)
                R[f] = *reinterpret_cast<const float4*>(xbase + f * 16 * D + (c + 1) * 64);
            const uint32_t PNn = b ? (sb + OFF_PN0) : (sb + OFF_PN1);
#pragma unroll
            for (int it = 0; it < 4; ++it) {
                int idx = tid + 256 * it;
                int row = idx >> 2, u = idx & 3;
                CP16(PNn + row * 80 + u * 16, g_pn8 + row * D + (c + 1) * 64 + u * 16);
            }
            CP_COMMIT();
        }
        // FP8 MMA: warp computes rows [wm1*32,+32) x cols [wn1*64,+64), 2 k32-steps
#pragma unroll
        for (int ks = 0; ks < 2; ++ks) {
            uint32_t a0[2], a1[2], a2[2], a3[2];
#pragma unroll
            for (int mt = 0; mt < 2; ++mt)
                ldsm_x4(a0[mt], a1[mt], a2[mt], a3[mt], XB + aoff1 + mt * 16 * 80 + ks * 32);
#pragma unroll
            for (int p = 0; p < 4; ++p) {
                uint32_t b0, b1, b2, b3;
                ldsm_x4(b0, b1, b2, b3, PN + boff1 + p * 16 * 80 + ks * 32);
#pragma unroll
                for (int mt = 0; mt < 2; ++mt) {
                    mma8(acc[mt][2 * p],     a0[mt], a1[mt], a2[mt], a3[mt], b0, b1);
                    mma8(acc[mt][2 * p + 1], a0[mt], a1[mt], a2[mt], a3[mt], b2, b3);
                }
            }
        }
    }
    __syncthreads();   // all phase-1 reads done before overlay reuse

    // ---- kick off PW chunk 0 staging (overlaps softmax) ----
#pragma unroll
    for (int it = 0; it < 16; ++it) {
        int idx = tid + 256 * it;           // 0..4095 16B units
        int row = idx >> 5, u = idx & 31;   // 128 rows x 32 units
        CP16(sb + OFF_PW + row * 528 + u * 16,
             reinterpret_cast<const char*>(g_pwt) + row * 512 + u * 16);
    }
    CP_COMMIT();

    // ---- softmax: scale by inv[row], exp, write bf16 exp tile + partial sums ----
#pragma unroll
    for (int mt = 0; mt < 2; ++mt) {
        const int r0 = wm1 * 32 + mt * 16 + g, r1 = r0 + 8;
        const float iv0 = inv[r0], iv1 = inv[r1];
        float s0 = 0.f, s1 = 0.f;
#pragma unroll
        for (int nt = 0; nt < 8; ++nt) {
            float e0 = __expf(acc[mt][nt][0] * iv0);
            float e1 = __expf(acc[mt][nt][1] * iv0);
            float e2 = __expf(acc[mt][nt][2] * iv1);
            float e3 = __expf(acc[mt][nt][3] * iv1);
            const uint32_t cb = (wn1 * 64 + nt * 8 + 2 * q) * 2;
            *reinterpret_cast<uint32_t*>(smem + OFF_EXP + r0 * 528 + cb) = packbf(e0, e1);
            *reinterpret_cast<uint32_t*>(smem + OFF_EXP + r1 * 528 + cb) = packbf(e2, e3);
            s0 += e0 + e1; s1 += e2 + e3;
        }
        s0 += __shfl_xor_sync(0xffffffffu, s0, 1);
        s0 += __shfl_xor_sync(0xffffffffu, s0, 2);
        s1 += __shfl_xor_sync(0xffffffffu, s1, 1);
        s1 += __shfl_xor_sync(0xffffffffu, s1, 2);
        if (q == 0) { parts[wn1 * 64 + r0] = s0; parts[wn1 * 64 + r1] = s1; }
    }
    __syncthreads();
    if (tid < 64) {
        float s = parts[tid] + parts[64 + tid] + parts[128 + tid] + parts[192 + tid];
        invS[tid] = 1.f / s;
    }

    // ---- Phase 3 (bf16): out[64][768] = exp @ PWT^T (6 e-chunks of 128) ----
    const int wm3 = w & 1, wn3 = w >> 1;      // 2 M groups x 4 N groups (32x32/warp)
    const uint32_t aoff3 = (wm3 * 32 + (lane & 7) + ((lane >> 3) & 1) * 8) * 528 + ((lane >> 4) & 1) * 16;
    const uint32_t boff3 = (wn3 * 32 + (lane & 7) + ((lane >> 4) & 1) * 8) * 528 + ((lane >> 3) & 1) * 16;

    for (int j = 0; j < 6; ++j) {
        CP_WAIT0();
        __syncthreads();                      // PW chunk j ready (and invS visible at j=0)

        float acc2[2][4][4];
#pragma unroll
        for (int mt = 0; mt < 2; ++mt)
#pragma unroll
            for (int nt = 0; nt < 4; ++nt)
#pragma unroll
                for (int jj = 0; jj < 4; ++jj) acc2[mt][nt][jj] = 0.f;

#pragma unroll
        for (int ks = 0; ks < 16; ++ks) {
            uint32_t b0, b1, b2, b3, b4, b5, b6, b7;
            ldsm_x4(b0, b1, b2, b3, sb + OFF_PW + boff3 + ks * 32);
            ldsm_x4(b4, b5, b6, b7, sb + OFF_PW + boff3 + 16 * 528 + ks * 32);
#pragma unroll
            for (int mt = 0; mt < 2; ++mt) {
                uint32_t a0, a1, a2, a3;
                ldsm_x4(a0, a1, a2, a3, sb + OFF_EXP + aoff3 + mt * 16 * 528 + ks * 32);
                mma4(acc2[mt][0], a0, a1, a2, a3, b0, b1);
                mma4(acc2[mt][1], a0, a1, a2, a3, b2, b3);
                mma4(acc2[mt][2], a0, a1, a2, a3, b4, b5);
                mma4(acc2[mt][3], a0, a1, a2, a3, b6, b7);
            }
        }
        __syncthreads();                      // all PW reads done
        if (j < 5) {
#pragma unroll
            for (int it = 0; it < 16; ++it) {
                int idx = tid + 256 * it;
                int row = idx >> 5, u = idx & 31;
                CP16(sb + OFF_PW + row * 528 + u * 16,
                     reinterpret_cast<const char*>(g_pwt) + ((j + 1) * 128 + row) * 512 + u * 16);
            }
            CP_COMMIT();
        }
        // epilogue (overlaps next PW load): divide by exp-sum, add bias, store
#pragma unroll
        for (int mt = 0; mt < 2; ++mt) {
            const int r0 = wm3 * 32 + mt * 16 + g, r1 = r0 + 8;
            const float is0 = invS[r0], is1 = invS[r1];
#pragma unroll
            for (int nt = 0; nt < 4; ++nt) {
                const int cc = j * 128 + wn3 * 32 + nt * 8 + 2 * q;
                const float2 bv = *reinterpret_cast<const float2*>(bias + cc);
                *reinterpret_cast<float2*>(out + (m0 + r0) * D + cc) =
                    make_float2(acc2[mt][nt][0] * is0 + bv.x, acc2[mt][nt][1] * is0 + bv.y);
                *reinterpret_cast<float2*>(out + (m0 + r1) * D + cc) =
                    make_float2(acc2[mt][nt][2] * is1 + bv.x, acc2[mt][nt][3] * is1 + bv.y);
            }
        }
    }
}

// ---------------------------------------------------------------------------
extern "C" void kernel_launch(void* const* d_in, const int* in_sizes, int n_in,
                              void* d_out, int out_size) {
    const float* x = (const float*)d_in[0];
    const float* P = (const float*)d_in[1];
    const float* W = (const float*)d_in[2];
    const float* b = (const float*)d_in[3];
    float* out = (float*)d_out;

    cudaFuncSetAttribute(main_kernel, cudaFuncAttributeMaxDynamicSharedMemorySize, SMEM_MAIN);

    prep_kernel<<<448, 256>>>(P, W);

    int rows = in_sizes[0] / D;               // 131072
    main_kernel<<<rows / 64, 256, SMEM_MAIN>>>(x, b, out);
}

// round 9
// speedup vs baseline: 1.3681x; 1.0161x over previous
#include <cuda_runtime.h>
#include <cuda_bf16.h>
#include <cstdint>

#define D  768
#define KP 256

__device__ __align__(16) uint8_t g_pn8[KP * D];    // normalized prototypes e4m3 [k][d]
__device__ __align__(16) uint8_t g_pwt8[D * KP];   // e4m3( P @ W^T / 256 * 64 ) : [e][k]

// ---------------------------------------------------------------------------
__device__ __forceinline__ uint32_t smem_u32(const void* p) {
    uint32_t a;
    asm("{ .reg .u64 t; cvta.to.shared.u64 t, %1; cvt.u32.u64 %0, t; }" : "=r"(a) : "l"(p));
    return a;
}
__device__ __forceinline__ uint16_t packe4m3(float lo, float hi) {
    uint16_t h;
    asm("cvt.rn.satfinite.e4m3x2.f32 %0, %1, %2;" : "=h"(h) : "f"(hi), "f"(lo));
    return h;
}
__device__ __forceinline__ void ldsm_x4(uint32_t& r0, uint32_t& r1, uint32_t& r2, uint32_t& r3,
                                        uint32_t addr) {
    asm volatile("ldmatrix.sync.aligned.m8n8.x4.shared.b16 {%0,%1,%2,%3}, [%4];"
                 : "=r"(r0), "=r"(r1), "=r"(r2), "=r"(r3) : "r"(addr));
}
__device__ __forceinline__ void mma8(float* c, uint32_t a0, uint32_t a1, uint32_t a2, uint32_t a3,
                                     uint32_t b0, uint32_t b1) {
    asm volatile(
        "mma.sync.aligned.m16n8k32.row.col.f32.e4m3.e4m3.f32 "
        "{%0,%1,%2,%3}, {%4,%5,%6,%7}, {%8,%9}, {%0,%1,%2,%3};"
        : "+f"(c[0]), "+f"(c[1]), "+f"(c[2]), "+f"(c[3])
        : "r"(a0), "r"(a1), "r"(a2), "r"(a3), "r"(b0), "r"(b1));
}
#define CP16(dst, src) asm volatile("cp.async.cg.shared.global [%0], [%1], 16;" :: "r"(dst), "l"(src))
#define CP_COMMIT()    asm volatile("cp.async.commit_group;" ::: "memory")
#define CP_WAIT0()     asm volatile("cp.async.wait_group 0;" ::: "memory")

// ---------------------------------------------------------------------------
// Merged prep kernel: blocks [0,256) normalize prototypes -> e4m3; rest build PWT(e4m3,x64)
// ---------------------------------------------------------------------------
__global__ void prep_kernel(const float* __restrict__ P, const float* __restrict__ W) {
    __shared__ float Pt[256 * 33 + 8];
    __shared__ float Wt[4 * 33];
    if (blockIdx.x < 256) {
        float* red = Pt;
        int k = blockIdx.x;
        const float* row = P + k * D;
        float s = 0.f;
        for (int d = threadIdx.x; d < D; d += 256) { float v = row[d]; s += v * v; }
#pragma unroll
        for (int o = 16; o; o >>= 1) s += __shfl_xor_sync(0xffffffffu, s, o);
        if ((threadIdx.x & 31) == 0) red[threadIdx.x >> 5] = s;
        __syncthreads();
        if (threadIdx.x == 0) {
            float t = 0.f;
#pragma unroll
            for (int i = 0; i < 8; ++i) t += red[i];
            red[0] = 1.f / fmaxf(sqrtf(t), 1e-12f);
        }
        __syncthreads();
        float iv = red[0];
        for (int p = threadIdx.x; p < D / 2; p += 256) {
            uint16_t h = packe4m3(row[2 * p] * iv, row[2 * p + 1] * iv);
            *reinterpret_cast<uint16_t*>(g_pn8 + k * D + 2 * p) = h;
        }
    } else {
        int e0 = (blockIdx.x - 256) * 4;
        int k  = threadIdx.x;
        float a0 = 0.f, a1 = 0.f, a2 = 0.f, a3 = 0.f;
        for (int dc = 0; dc < D; dc += 32) {
#pragma unroll
            for (int it = 0; it < 32; ++it) {
                int idx = threadIdx.x + 256 * it;
                int row = idx >> 5, d = idx & 31;
                Pt[row * 33 + d] = P[row * D + dc + d];
            }
            if (threadIdx.x < 128) {
                int e = threadIdx.x >> 5, d = threadIdx.x & 31;
                Wt[e * 33 + d] = W[(e0 + e) * D + dc + d];
            }
            __syncthreads();
#pragma unroll
            for (int d = 0; d < 32; ++d) {
                float p = Pt[k * 33 + d];
                a0 += p * Wt[0 * 33 + d];
                a1 += p * Wt[1 * 33 + d];
                a2 += p * Wt[2 * 33 + d];
                a3 += p * Wt[3 * 33 + d];
            }
            __syncthreads();
        }
        // scale: 1/256 (mixture) * 64 (fp8 dynamic-range boost, undone in epilogue)
        const float sc = 64.f / 256.f;
        g_pwt8[(e0 + 0) * KP + k] = (uint8_t)(packe4m3(a0 * sc, 0.f) & 0xff);
        g_pwt8[(e0 + 1) * KP + k] = (uint8_t)(packe4m3(a1 * sc, 0.f) & 0xff);
        g_pwt8[(e0 + 2) * KP + k] = (uint8_t)(packe4m3(a2 * sc, 0.f) & 0xff);
        g_pwt8[(e0 + 3) * KP + k] = (uint8_t)(packe4m3(a3 * sc, 0.f) & 0xff);
    }
}

// ---------------------------------------------------------------------------
// Main fused kernel: M_TILE=64, 256 threads, 2 CTAs/SM, FP8 GEMM1 + FP8 GEMM2
// ---------------------------------------------------------------------------
#define OFF_INV   0            // float[64]
#define OFF_INVS  256          // float[64]
#define OFF_PARTS 512          // float[4][64]
#define OFF_EXP   1536         // e4m3 [64][272B]  = 17408
#define OFF_PW    18944        // e4m3 [128][272B] = 34816
#define SMEM_MAIN 53760
// phase-1 overlays (e4m3 tiles, stride 80B):
#define OFF_XB0   1536                 // e4m3 [64][80]  = 5120
#define OFF_XB1   (1536 + 5120)
#define OFF_PN0   (1536 + 10240)       // e4m3 [256][80] = 20480
#define OFF_PN1   (1536 + 30720)

__global__ __launch_bounds__(256, 2)
void main_kernel(const float* __restrict__ x, const float* __restrict__ bias,
                 float* __restrict__ out) {
    extern __shared__ char smem[];
    const uint32_t sb = smem_u32(smem);
    const int tid = threadIdx.x, w = tid >> 5, lane = tid & 31;
    const int g = lane >> 2, q = lane & 3;
    const long m0 = (long)blockIdx.x * 64;

    float* inv   = reinterpret_cast<float*>(smem + OFF_INV);
    float* invS  = reinterpret_cast<float*>(smem + OFF_INVS);
    float* parts = reinterpret_cast<float*>(smem + OFF_PARTS);

    // ---- phase-1 tiling: wm1 = M half (32 rows), wn1 = N group (64 cols) ----
    const int wm1 = w & 1, wn1 = w >> 1;
    const int xr0 = tid >> 4, xc4 = tid & 15;
    const float* xbase = x + (m0 + xr0) * D + xc4 * 4;
    const uint32_t aoff1 = (wm1 * 32 + (lane & 7) + ((lane >> 3) & 1) * 8) * 80 + ((lane >> 4) & 1) * 16;
    const uint32_t boff1 = (wn1 * 64 + (lane & 7) + ((lane >> 4) & 1) * 8) * 80 + ((lane >> 3) & 1) * 16;

    float acc[2][8][4];
#pragma unroll
    for (int mt = 0; mt < 2; ++mt)
#pragma unroll
        for (int nt = 0; nt < 8; ++nt)
#pragma unroll
            for (int j = 0; j < 4; ++j) acc[mt][nt][j] = 0.f;

    float sq[4] = {0.f, 0.f, 0.f, 0.f};

    // ---- prologue: prefetch x chunk 0, cp.async pn chunk 0 ----
    float4 R[4];
#pragma unroll
    for (int f = 0; f < 4; ++f)
        R[f] = *reinterpret_cast<const float4*>(xbase + f * 16 * D);
#pragma unroll
    for (int it = 0; it < 4; ++it) {
        int idx = tid + 256 * it;          // 0..1023
        int row = idx >> 2, u = idx & 3;   // 256 rows x 4 16B units
        CP16(sb + OFF_PN0 + row * 80 + u * 16, g_pn8 + row * D + u * 16);
    }
    CP_COMMIT();

    // ---- Phase 1 (FP8): sim[64][256] = x @ pn^T (12 K-chunks of 64) ----
    for (int c = 0; c < 12; ++c) {
        const int b = c & 1;
        const uint32_t XB = b ? (sb + OFF_XB1) : (sb + OFF_XB0);
        const uint32_t PN = b ? (sb + OFF_PN1) : (sb + OFF_PN0);
#pragma unroll
        for (int f = 0; f < 4; ++f) {
            float4 v = R[f];
            sq[f] += v.x * v.x + v.y * v.y + v.z * v.z + v.w * v.w;
            uint32_t word = (uint32_t)packe4m3(v.x, v.y) |
                            ((uint32_t)packe4m3(v.z, v.w) << 16);
            *reinterpret_cast<uint32_t*>(smem + (XB - sb) + (xr0 + 16 * f) * 80 + xc4 * 4) = word;
        }
        if (c == 11) {
#pragma unroll
            for (int f = 0; f < 4; ++f) {
                float s = sq[f];
                s += __shfl_xor_sync(0xffffffffu, s, 1);
                s += __shfl_xor_sync(0xffffffffu, s, 2);
                s += __shfl_xor_sync(0xffffffffu, s, 4);
                s += __shfl_xor_sync(0xffffffffu, s, 8);
                if ((tid & 15) == 0) inv[xr0 + 16 * f] = 1.f / fmaxf(sqrtf(s), 1e-12f);
            }
        }
        CP_WAIT0();
        __syncthreads();
        if (c < 11) {
#pragma unroll
            for (int f = 0; f < 4; ++f)
                R[f] = *reinterpret_cast<const float4*>(xbase + f * 16 * D + (c + 1) * 64);
            const uint32_t PNn = b ? (sb + OFF_PN0) : (sb + OFF_PN1);
#pragma unroll
            for (int it = 0; it < 4; ++it) {
                int idx = tid + 256 * it;
                int row = idx >> 2, u = idx & 3;
                CP16(PNn + row * 80 + u * 16, g_pn8 + row * D + (c + 1) * 64 + u * 16);
            }
            CP_COMMIT();
        }
#pragma unroll
        for (int ks = 0; ks < 2; ++ks) {
            uint32_t a0[2], a1[2], a2[2], a3[2];
#pragma unroll
            for (int mt = 0; mt < 2; ++mt)
                ldsm_x4(a0[mt], a1[mt], a2[mt], a3[mt], XB + aoff1 + mt * 16 * 80 + ks * 32);
#pragma unroll
            for (int p = 0; p < 4; ++p) {
                uint32_t b0, b1, b2, b3;
                ldsm_x4(b0, b1, b2, b3, PN + boff1 + p * 16 * 80 + ks * 32);
#pragma unroll
                for (int mt = 0; mt < 2; ++mt) {
                    mma8(acc[mt][2 * p],     a0[mt], a1[mt], a2[mt], a3[mt], b0, b1);
                    mma8(acc[mt][2 * p + 1], a0[mt], a1[mt], a2[mt], a3[mt], b2, b3);
                }
            }
        }
    }
    __syncthreads();   // all phase-1 reads done before overlay reuse

    // ---- kick off PW chunk 0 staging (overlaps softmax) ----
#pragma unroll
    for (int it = 0; it < 8; ++it) {
        int idx = tid + 256 * it;           // 0..2047 16B units
        int row = idx >> 4, u = idx & 15;   // 128 rows x 16 units (256 e4m3)
        CP16(sb + OFF_PW + row * 272 + u * 16, g_pwt8 + row * KP + u * 16);
    }
    CP_COMMIT();

    // ---- softmax: scale by inv[row], exp, write e4m3 exp tile + partial sums ----
#pragma unroll
    for (int mt = 0; mt < 2; ++mt) {
        const int r0 = wm1 * 32 + mt * 16 + g, r1 = r0 + 8;
        const float iv0 = inv[r0], iv1 = inv[r1];
        float s0 = 0.f, s1 = 0.f;
#pragma unroll
        for (int nt = 0; nt < 8; ++nt) {
            float e0 = __expf(acc[mt][nt][0] * iv0);
            float e1 = __expf(acc[mt][nt][1] * iv0);
            float e2 = __expf(acc[mt][nt][2] * iv1);
            float e3 = __expf(acc[mt][nt][3] * iv1);
            const uint32_t cb = wn1 * 64 + nt * 8 + 2 * q;   // e4m3 col == byte
            *reinterpret_cast<uint16_t*>(smem + OFF_EXP + r0 * 272 + cb) = packe4m3(e0, e1);
            *reinterpret_cast<uint16_t*>(smem + OFF_EXP + r1 * 272 + cb) = packe4m3(e2, e3);
            s0 += e0 + e1; s1 += e2 + e3;
        }
        s0 += __shfl_xor_sync(0xffffffffu, s0, 1);
        s0 += __shfl_xor_sync(0xffffffffu, s0, 2);
        s1 += __shfl_xor_sync(0xffffffffu, s1, 1);
        s1 += __shfl_xor_sync(0xffffffffu, s1, 2);
        if (q == 0) { parts[wn1 * 64 + r0] = s0; parts[wn1 * 64 + r1] = s1; }
    }
    __syncthreads();
    if (tid < 64) {
        float s = parts[tid] + parts[64 + tid] + parts[128 + tid] + parts[192 + tid];
        invS[tid] = 1.f / (64.f * s);        // fold the x64 PWT scale back out
    }

    // ---- Phase 3 (FP8): out[64][768] = exp @ PWT^T (6 e-chunks of 128) ----
    const int wm3 = w & 1, wn3 = w >> 1;      // 2 M groups x 4 N groups (32x32/warp)
    const uint32_t aoff3 = (wm3 * 32 + (lane & 7) + ((lane >> 3) & 1) * 8) * 272 + ((lane >> 4) & 1) * 16;
    const uint32_t boff3 = (wn3 * 32 + (lane & 7) + ((lane >> 4) & 1) * 8) * 272 + ((lane >> 3) & 1) * 16;

    for (int j = 0; j < 6; ++j) {
        CP_WAIT0();
        __syncthreads();                      // PW chunk j ready (and invS visible at j=0)

        float acc2[2][4][4];
#pragma unroll
        for (int mt = 0; mt < 2; ++mt)
#pragma unroll
            for (int nt = 0; nt < 4; ++nt)
#pragma unroll
                for (int jj = 0; jj < 4; ++jj) acc2[mt][nt][jj] = 0.f;

#pragma unroll
        for (int ks = 0; ks < 8; ++ks) {      // 8 k32-steps over K=256
            uint32_t b0, b1, b2, b3, b4, b5, b6, b7;
            ldsm_x4(b0, b1, b2, b3, sb + OFF_PW + boff3 + ks * 32);
            ldsm_x4(b4, b5, b6, b7, sb + OFF_PW + boff3 + 16 * 272 + ks * 32);
#pragma unroll
            for (int mt = 0; mt < 2; ++mt) {
                uint32_t a0, a1, a2, a3;
                ldsm_x4(a0, a1, a2, a3, sb + OFF_EXP + aoff3 + mt * 16 * 272 + ks * 32);
                mma8(acc2[mt][0], a0, a1, a2, a3, b0, b1);
                mma8(acc2[mt][1], a0, a1, a2, a3, b2, b3);
                mma8(acc2[mt][2], a0, a1, a2, a3, b4, b5);
                mma8(acc2[mt][3], a0, a1, a2, a3, b6, b7);
            }
        }
        __syncthreads();                      // all PW reads done
        if (j < 5) {
#pragma unroll
            for (int it = 0; it < 8; ++it) {
                int idx = tid + 256 * it;
                int row = idx >> 4, u = idx & 15;
                CP16(sb + OFF_PW + row * 272 + u * 16,
                     g_pwt8 + ((j + 1) * 128 + row) * KP + u * 16);
            }
            CP_COMMIT();
        }
        // epilogue (overlaps next PW load): scale by invS (incl 1/64), add bias, store
#pragma unroll
        for (int mt = 0; mt < 2; ++mt) {
            const int r0 = wm3 * 32 + mt * 16 + g, r1 = r0 + 8;
            const float is0 = invS[r0], is1 = invS[r1];
#pragma unroll
            for (int nt = 0; nt < 4; ++nt) {
                const int cc = j * 128 + wn3 * 32 + nt * 8 + 2 * q;
                const float2 bv = *reinterpret_cast<const float2*>(bias + cc);
                *reinterpret_cast<float2*>(out + (m0 + r0) * D + cc) =
                    make_float2(acc2[mt][nt][0] * is0 + bv.x, acc2[mt][nt][1] * is0 + bv.y);
                *reinterpret_cast<float2*>(out + (m0 + r1) * D + cc) =
                    make_float2(acc2[mt][nt][2] * is1 + bv.x, acc2[mt][nt][3] * is1 + bv.y);
            }
        }
    }
}

// ---------------------------------------------------------------------------
extern "C" void kernel_launch(void* const* d_in, const int* in_sizes, int n_in,
                              void* d_out, int out_size) {
    const float* x = (const float*)d_in[0];
    const float* P = (const float*)d_in[1];
    const float* W = (const float*)d_in[2];
    const float* b = (const float*)d_in[3];
    float* out = (float*)d_out;

    cudaFuncSetAttribute(main_kernel, cudaFuncAttributeMaxDynamicSharedMemorySize, SMEM_MAIN);

    prep_kernel<<<448, 256>>>(P, W);

    int rows = in_sizes[0] / D;               // 131072
    main_kernel<<<rows / 64, 256, SMEM_MAIN>>>(x, b, out);
}